// round 12
// baseline (speedup 1.0000x reference)
#include <cuda_runtime.h>
#include <cuda_bf16.h>
#include <math.h>
#include <stdint.h>

// ---------------- problem constants ----------------
#define BATCH  16384
#define NNUM   16
#define NCAT   24
#define KCLS   16
#define CATDIM 384
#define DIN    400
#define DIMT   1024
#define HIDN   1024
#define NPAD2  512          // padded DIN for mlp2 output
#define TSTEPS 1000
#define TPAD   1024

#define LOGK_F 2.772588722239781f
#define CL_F   (-69.07755278982137f)

// ---------------- device scratch ----------------
__device__ float d_LOG_A[TSTEPS], d_LOG_1M_A[TSTEPS];
__device__ float d_LOG_CA[TSTEPS], d_LOG_1M_CA[TSTEPS];
__device__ float d_SQAC[TSTEPS], d_SQ1MAC[TSTEPS];
__device__ float d_KLP;
__device__ int   d_t64, d_c64;
__device__ int   d_TT[BATCH];
__device__ int   d_CAT[BATCH * NCAT];
__device__ int   d_SAMP[BATCH * NCAT];
__device__ float d_XNT[(size_t)BATCH * NNUM];
__device__ float d_SUMALL[DIMT];

__device__ __nv_bfloat16 d_E0H[TPAD * DIMT], d_E0L[TPAD * DIMT];
__device__ __nv_bfloat16 d_E1H[TPAD * DIMT], d_E1L[TPAD * DIMT];
__device__ float         d_EMB[TPAD * DIMT];
__device__ __nv_bfloat16 d_W1TH[DIMT * DIMT], d_W1TL[DIMT * DIMT];   // te_w1^T
__device__ __nv_bfloat16 d_W2TH[DIMT * DIMT], d_W2TL[DIMT * DIMT];   // te_w2^T
__device__ __nv_bfloat16 d_M1TH[HIDN * DIMT], d_M1TL[HIDN * DIMT];   // mlp_w1^T
__device__ __nv_bfloat16 d_M2TH[NPAD2 * HIDN], d_M2TL[NPAD2 * HIDN]; // mlp_w2^T padded
__device__ __nv_bfloat16 d_HH[(size_t)BATCH * DIMT], d_HL[(size_t)BATCH * DIMT];
__device__ __nv_bfloat16 d_UH[(size_t)BATCH * DIMT], d_UL[(size_t)BATCH * DIMT];
__device__ float         d_OUT[(size_t)BATCH * NPAD2];
__device__ float         d_B2P[NPAD2];
__device__ float d_PART[BATCH / 8];

// ---------------- helpers ----------------
__device__ __forceinline__ float laddexp(float a, float b) {
    float m = fmaxf(a, b);
    return m + logf(expf(a - m) + expf(b - m));
}
__device__ __forceinline__ uint32_t smem_u32(const void* p) {
    return (uint32_t)__cvta_generic_to_shared(p);
}
#define SWZ128(o) ((o) ^ (((o) >> 3) & 0x70))

__device__ __forceinline__ void ldsm4(uint32_t* r, uint32_t addr) {
    asm volatile("ldmatrix.sync.aligned.m8n8.x4.shared.b16 {%0,%1,%2,%3}, [%4];"
        : "=r"(r[0]), "=r"(r[1]), "=r"(r[2]), "=r"(r[3]) : "r"(addr));
}
__device__ __forceinline__ void mma16816(float* c, const uint32_t* a, uint32_t b0, uint32_t b1) {
    asm volatile("mma.sync.aligned.m16n8k16.row.col.f32.bf16.bf16.f32 "
        "{%0,%1,%2,%3}, {%4,%5,%6,%7}, {%8,%9}, {%0,%1,%2,%3};"
        : "+f"(c[0]), "+f"(c[1]), "+f"(c[2]), "+f"(c[3])
        : "r"(a[0]), "r"(a[1]), "r"(a[2]), "r"(a[3]), "r"(b0), "r"(b1));
}

// ---------------- schedules ----------------
__global__ void sched_kernel() {
    __shared__ double s[1024];
    int i = threadIdx.x;
    const double PI = 3.14159265358979323846;
    double la = 0.0;
    if (i < TSTEPS) {
        double u0 = (double)i / (double)TSTEPS;
        double u1 = (double)(i + 1) / (double)TSTEPS;
        double c0 = cos((u0 + 0.008) / 1.008 * PI / 2.0); double ab0 = c0 * c0;
        double c1 = cos((u1 + 0.008) / 1.008 * PI / 2.0); double ab1 = c1 * c1;
        double beta = 1.0 - ab1 / ab0;
        if (beta > 0.999) beta = 0.999;
        la = log(1.0 - beta);
    }
    s[i] = la;
    __syncthreads();
    #pragma unroll
    for (int off = 1; off < 1024; off <<= 1) {
        double v = (i >= off) ? s[i - off] : 0.0;
        __syncthreads();
        s[i] += v;
        __syncthreads();
    }
    if (i < TSTEPS) {
        double lca = s[i];
        d_LOG_A[i]     = (float)la;
        d_LOG_1M_A[i]  = (float)log(1.0 - exp(la) + 1e-40);
        d_LOG_CA[i]    = (float)lca;
        d_LOG_1M_CA[i] = (float)log(1.0 - exp(lca) + 1e-40);
        double ac = exp(lca);
        d_SQAC[i]   = (float)sqrt(ac);
        d_SQ1MAC[i] = (float)sqrt(1.0 - ac);
    }
    __syncthreads();
    if (i == 0) {
        float lcaT = d_LOG_CA[TSTEPS - 1], l1mT = d_LOG_1M_CA[TSTEPS - 1];
        float hT = laddexp(lcaT, l1mT - LOGK_F);
        float oT = laddexp(CL_F + lcaT, l1mT - LOGK_F);
        d_KLP = (float)NCAT * (expf(hT) * (hT + LOGK_F) + 15.0f * expf(oT) * (oT + LOGK_F));
    }
}

// ---------------- dtype sniff + fused conversions ----------------
__global__ void detect_kernel(const int* __restrict__ traw, const int* __restrict__ craw) {
    if (threadIdx.x != 0) return;
    int z = 1;
    for (int i = 0; i < 64; i++) if (traw[2 * i + 1] != 0) { z = 0; break; }
    d_t64 = z;
    z = 1;
    for (int i = 0; i < 64; i++) if (craw[2 * i + 1] != 0) { z = 0; break; }
    d_c64 = z;
}
__global__ void convert_all_kernel(const int* __restrict__ traw, const int* __restrict__ craw,
                                   const float* __restrict__ b2) {
    int i = blockIdx.x * blockDim.x + threadIdx.x;
    if (i < BATCH) d_TT[i] = d_t64 ? traw[2 * i] : traw[i];
    if (i < BATCH * NCAT) d_CAT[i] = d_c64 ? craw[2 * i] : craw[i];
    if (i < NPAD2) d_B2P[i] = (i < DIN) ? b2[i] : 0.f;
}

// ---------------- timestep embedding (hi/lo bf16, padded rows zero) --------
__global__ void temb_kernel() {
    int t = blockIdx.x;
    int j = blockIdx.y * blockDim.x + threadIdx.x;
    float v = 0.f;
    if (t < TSTEPS) {
        int h = j & 511;
        float freq = expf(-9.210340371976184f * (float)h / 512.0f);
        float arg = (float)t * freq;
        v = (j < 512) ? cosf(arg) : sinf(arg);
    }
    __nv_bfloat16 hi = __float2bfloat16(v);
    __nv_bfloat16 lo = __float2bfloat16(v - __bfloat162float(hi));
    d_E0H[t * DIMT + j] = hi;
    d_E0L[t * DIMT + j] = lo;
}

// ---------------- weight transposes (te_w1, te_w2, mlp_w1, mlp_w2) --------
__device__ __forceinline__ void do_transpose(
    const float* __restrict__ in, int R, int C, int Rpad,
    __nv_bfloat16* __restrict__ oh, __nv_bfloat16* __restrict__ ol,
    int bx, int by)
{
    __shared__ float tl[32][33];
    int c0 = bx * 32, r0 = by * 32;
    #pragma unroll
    for (int k = 0; k < 4; k++) {
        int r = r0 + threadIdx.y + k * 8;
        int c = c0 + threadIdx.x;
        float v = (r < R && c < C) ? in[(size_t)r * C + c] : 0.f;
        tl[threadIdx.x][threadIdx.y + k * 8] = v;
    }
    __syncthreads();
    #pragma unroll
    for (int k = 0; k < 4; k++) {
        int c = c0 + threadIdx.y + k * 8;   // out row
        int r = r0 + threadIdx.x;           // out col
        float v = tl[threadIdx.y + k * 8][threadIdx.x];
        __nv_bfloat16 h = __float2bfloat16(v);
        oh[(size_t)c * Rpad + r] = h;
        ol[(size_t)c * Rpad + r] = __float2bfloat16(v - __bfloat162float(h));
    }
}

__global__ void transpose_all_kernel(
    const float* __restrict__ te_w1, const float* __restrict__ te_w2,
    const float* __restrict__ mlp_w1, const float* __restrict__ mlp_w2)
{
    int b = blockIdx.x;
    if (b < 1024) {
        do_transpose(te_w1, DIMT, DIMT, DIMT, d_W1TH, d_W1TL, b & 31, b >> 5);
    } else if (b < 2048) {
        b -= 1024;
        do_transpose(te_w2, DIMT, DIMT, DIMT, d_W2TH, d_W2TL, b & 31, b >> 5);
    } else if (b < 3072) {
        b -= 2048;
        do_transpose(mlp_w1, DIMT, HIDN, DIMT, d_M1TH, d_M1TL, b & 31, b >> 5);
    } else {
        b -= 3072;                               // 16 x 32 blocks
        do_transpose(mlp_w2, HIDN, DIN, HIDN, d_M2TH, d_M2TL, b & 15, b >> 4);
    }
}

// ---------------- sum of categorical proj_w rows ----------------
__global__ void sumall_kernel(const float* __restrict__ proj_w) {
    int j = blockIdx.x * blockDim.x + threadIdx.x;
    if (j >= DIMT) return;
    float s = 0.f;
    for (int r = NNUM; r < DIN; r++) s += proj_w[(size_t)r * DIMT + j];
    d_SUMALL[j] = s;
}

// ---------------- gumbel sampling + numeric noising ----------------------
__global__ void sample_kernel(const float* __restrict__ x_num,
                              const float* __restrict__ noise,
                              const float* __restrict__ gumbel) {
    int i = blockIdx.x * blockDim.x + threadIdx.x;
    if (i < BATCH * NNUM) {
        int b = i >> 4;
        int t = d_TT[b];
        d_XNT[i] = d_SQAC[t] * x_num[i] + d_SQ1MAC[t] * noise[i];
    }
    if (i < BATCH * NCAT) {
        int b = i / NCAT, c = i - b * NCAT;
        int t = d_TT[b];
        int hot = d_CAT[i];
        float hv = laddexp(d_LOG_CA[t], d_LOG_1M_CA[t] - LOGK_F);
        float ov = laddexp(CL_F + d_LOG_CA[t], d_LOG_1M_CA[t] - LOGK_F);
        const float* gp = gumbel + (size_t)b * CATDIM + c * KCLS;
        float best = -1e30f; int bi = 0;
        #pragma unroll
        for (int k = 0; k < KCLS; k++) {
            float g = -logf(-logf(gp[k] + 1e-30f) + 1e-30f);
            float v = g + ((k == hot) ? hv : ov);
            if (v > best) { best = v; bi = k; }
        }
        d_SAMP[i] = bi;
    }
}

// ---------------- direct sparse proj: h = x_in@W + b + emb[t] (fp32) ------
// Exploits one-hot structure: h = emb + bias + CL*SUMALL + sum_i xnt*W_num
//                                 - CL * sum_c W[hot_c].
// CTA = 128 batch rows x 128 cols; all 400 W rows for the col slice in smem.
#define BH_SMEM (400*128*4 + 128*16*4 + 128*24*4)   // 225280 B
__global__ __launch_bounds__(256) void build_h_kernel(
    const float* __restrict__ proj_w, const float* __restrict__ proj_b) {
    extern __shared__ float sm[];
    float* W    = sm;                        // [400][128]
    float* xnt  = sm + 400 * 128;            // [128][16]
    int*   samp = (int*)(sm + 400 * 128 + 128 * 16); // [128][24]
    int colBase = blockIdx.x * 128;
    int rowBase = blockIdx.y * 128;
    int tid = threadIdx.x;

    for (int id = tid; id < 400 * 32; id += 256) {
        int r = id >> 5, c4 = (id & 31) * 4;
        *reinterpret_cast<float4*>(&W[r * 128 + c4]) =
            *reinterpret_cast<const float4*>(&proj_w[(size_t)r * DIMT + colBase + c4]);
    }
    for (int id = tid; id < 128 * NNUM; id += 256)
        xnt[id] = d_XNT[(size_t)rowBase * NNUM + id];
    for (int id = tid; id < 128 * NCAT; id += 256)
        samp[id] = d_SAMP[(size_t)rowBase * NCAT + id];
    __syncthreads();

    int w = tid >> 5, lane = tid & 31;
    int col = lane * 4;
    #pragma unroll 1
    for (int rr = 0; rr < 16; rr++) {
        int row = w * 16 + rr;
        int b = rowBase + row;
        int t = d_TT[b];
        float4 e4 = *reinterpret_cast<const float4*>(&d_EMB[(size_t)t * DIMT + colBase + col]);
        float4 b4 = *reinterpret_cast<const float4*>(&proj_b[colBase + col]);
        float4 s4 = *reinterpret_cast<const float4*>(&d_SUMALL[colBase + col]);
        float ax = e4.x + b4.x + CL_F * s4.x;
        float ay = e4.y + b4.y + CL_F * s4.y;
        float az = e4.z + b4.z + CL_F * s4.z;
        float aw = e4.w + b4.w + CL_F * s4.w;
        #pragma unroll
        for (int i = 0; i < NNUM; i++) {
            float xv = xnt[row * NNUM + i];
            float4 wv = *reinterpret_cast<float4*>(&W[i * 128 + col]);
            ax = fmaf(xv, wv.x, ax); ay = fmaf(xv, wv.y, ay);
            az = fmaf(xv, wv.z, az); aw = fmaf(xv, wv.w, aw);
        }
        float gx = 0.f, gy = 0.f, gz = 0.f, gw = 0.f;
        #pragma unroll
        for (int c = 0; c < NCAT; c++) {
            int rsel = NNUM + c * KCLS + samp[row * NCAT + c];
            float4 wv = *reinterpret_cast<float4*>(&W[rsel * 128 + col]);
            gx += wv.x; gy += wv.y; gz += wv.z; gw += wv.w;
        }
        ax -= CL_F * gx; ay -= CL_F * gy; az -= CL_F * gz; aw -= CL_F * gw;

        __nv_bfloat16 h0 = __float2bfloat16(ax), h1 = __float2bfloat16(ay);
        __nv_bfloat16 h2 = __float2bfloat16(az), h3 = __float2bfloat16(aw);
        __nv_bfloat162 hh0, hh1, ll0, ll1;
        hh0.x = h0; hh0.y = h1; hh1.x = h2; hh1.y = h3;
        ll0.x = __float2bfloat16(ax - __bfloat162float(h0));
        ll0.y = __float2bfloat16(ay - __bfloat162float(h1));
        ll1.x = __float2bfloat16(az - __bfloat162float(h2));
        ll1.y = __float2bfloat16(aw - __bfloat162float(h3));
        size_t o = (size_t)b * DIMT + colBase + col;
        *reinterpret_cast<__nv_bfloat162*>(&d_HH[o])     = hh0;
        *reinterpret_cast<__nv_bfloat162*>(&d_HH[o + 2]) = hh1;
        *reinterpret_cast<__nv_bfloat162*>(&d_HL[o])     = ll0;
        *reinterpret_cast<__nv_bfloat162*>(&d_HL[o + 2]) = ll1;
    }
}

// ---------------- fused 3-term bf16 mma.sync GEMM, 3-stage pipeline -------
#define GSMEM_BYTES 196608
__global__ __launch_bounds__(256) void mma_gemm(
    const __nv_bfloat16* __restrict__ Ahi, const __nv_bfloat16* __restrict__ Alo,
    const __nv_bfloat16* __restrict__ Bhi, const __nv_bfloat16* __restrict__ Blo,
    const float* __restrict__ bias,
    float* __restrict__ outF, __nv_bfloat16* __restrict__ outH, __nv_bfloat16* __restrict__ outL,
    int Kelem, int ldOut, int mode)   // mode 0: fp32  1: relu->hi/lo  2: silu->hi/lo
{
    extern __shared__ char smem[];
    const uint32_t sbase = smem_u32(smem);      // 3 stages x 64KB: Ahi|Alo|Bhi|Blo
    int tid = threadIdx.x, wid = tid >> 5, lane = tid & 31;
    int wm = (wid & 3) * 32, wn = (wid >> 2) * 64;
    int rowBase = blockIdx.y * 128, colBase = blockIdx.x * 128;

    int KS = Kelem >> 6;

    int c0i = tid * 4;
    int ldRow = c0i >> 3;
    int ldUn  = c0i & 7;

    float acc[2][8][4];
    #pragma unroll
    for (int a = 0; a < 2; a++)
        #pragma unroll
        for (int b = 0; b < 8; b++)
            #pragma unroll
            for (int c = 0; c < 4; c++) acc[a][b][c] = 0.f;

    auto issue = [&](int s) {
        int kb = s << 6;
        int st = s % 3;
        const __nv_bfloat16* gaH = Ahi + (size_t)(rowBase + ldRow) * Kelem + kb + ldUn * 8;
        const __nv_bfloat16* gaL = Alo + (size_t)(rowBase + ldRow) * Kelem + kb + ldUn * 8;
        const __nv_bfloat16* gbH = Bhi + (size_t)(colBase + ldRow) * Kelem + kb + ldUn * 8;
        const __nv_bfloat16* gbL = Blo + (size_t)(colBase + ldRow) * Kelem + kb + ldUn * 8;
        uint32_t base = sbase + st * 65536;
        #pragma unroll
        for (int q = 0; q < 4; q++) {
            uint32_t off = SWZ128(ldRow * 128 + (ldUn + q) * 16);
            asm volatile("cp.async.cg.shared.global [%0], [%1], 16;" :: "r"(base + off),         "l"(gaH + q * 8));
            asm volatile("cp.async.cg.shared.global [%0], [%1], 16;" :: "r"(base + 16384 + off), "l"(gaL + q * 8));
            asm volatile("cp.async.cg.shared.global [%0], [%1], 16;" :: "r"(base + 32768 + off), "l"(gbH + q * 8));
            asm volatile("cp.async.cg.shared.global [%0], [%1], 16;" :: "r"(base + 49152 + off), "l"(gbL + q * 8));
        }
    };

    issue(0);
    asm volatile("cp.async.commit_group;\n" ::: "memory");
    if (KS > 1) issue(1);
    asm volatile("cp.async.commit_group;\n" ::: "memory");

    int aRowC = wm + (lane & 15);
    int aKC   = (lane & 16);
    int bRowC = wn + (lane & 7) + ((lane & 16) >> 1);
    int bKC   = (lane & 8) * 2;

    for (int s = 0; s < KS; s++) {
        asm volatile("cp.async.wait_group 1;\n" ::: "memory");
        __syncthreads();

        if (s + 2 < KS) issue(s + 2);
        asm volatile("cp.async.commit_group;\n" ::: "memory");

        uint32_t base = sbase + (s % 3) * 65536;
        uint32_t baAH = base, baAL = base + 16384, baBH = base + 32768, baBL = base + 49152;
        #pragma unroll
        for (int kk = 0; kk < 4; kk++) {
            uint32_t aH[2][4], aL[2][4], bH[4][4], bL[4][4];
            #pragma unroll
            for (int mi = 0; mi < 2; mi++) {
                uint32_t off = SWZ128((aRowC + mi * 16) * 128 + kk * 32 + aKC);
                ldsm4(aH[mi], baAH + off);
                ldsm4(aL[mi], baAL + off);
            }
            #pragma unroll
            for (int nt = 0; nt < 4; nt++) {
                uint32_t off = SWZ128((bRowC + nt * 16) * 128 + kk * 32 + bKC);
                ldsm4(bH[nt], baBH + off);
                ldsm4(bL[nt], baBL + off);
            }
            #pragma unroll
            for (int mi = 0; mi < 2; mi++)
                #pragma unroll
                for (int nt = 0; nt < 4; nt++) {
                    mma16816(acc[mi][nt * 2],     aH[mi], bH[nt][0], bH[nt][1]);
                    mma16816(acc[mi][nt * 2 + 1], aH[mi], bH[nt][2], bH[nt][3]);
                }
            #pragma unroll
            for (int mi = 0; mi < 2; mi++)
                #pragma unroll
                for (int nt = 0; nt < 4; nt++) {
                    mma16816(acc[mi][nt * 2],     aH[mi], bL[nt][0], bL[nt][1]);
                    mma16816(acc[mi][nt * 2 + 1], aH[mi], bL[nt][2], bL[nt][3]);
                }
            #pragma unroll
            for (int mi = 0; mi < 2; mi++)
                #pragma unroll
                for (int nt = 0; nt < 4; nt++) {
                    mma16816(acc[mi][nt * 2],     aL[mi], bH[nt][0], bH[nt][1]);
                    mma16816(acc[mi][nt * 2 + 1], aL[mi], bH[nt][2], bH[nt][3]);
                }
        }
    }

    // ---------------- epilogue ----------------
    #pragma unroll
    for (int mi = 0; mi < 2; mi++) {
        #pragma unroll
        for (int half = 0; half < 2; half++) {
            int r = rowBase + wm + mi * 16 + (lane >> 2) + half * 8;
            #pragma unroll
            for (int ni = 0; ni < 8; ni++) {
                int c = colBase + wn + ni * 8 + (lane & 3) * 2;
                float v0 = acc[mi][ni][half * 2 + 0] + bias[c];
                float v1 = acc[mi][ni][half * 2 + 1] + bias[c + 1];
                if (mode == 0) {
                    float2 v; v.x = v0; v.y = v1;
                    *reinterpret_cast<float2*>(&outF[(size_t)r * ldOut + c]) = v;
                } else {
                    if (mode == 1) {
                        v0 = fmaxf(v0, 0.f); v1 = fmaxf(v1, 0.f);
                    } else {
                        v0 = v0 / (1.f + expf(-v0)); v1 = v1 / (1.f + expf(-v1));
                    }
                    __nv_bfloat16 h0 = __float2bfloat16(v0), h1 = __float2bfloat16(v1);
                    __nv_bfloat162 hh, ll;
                    hh.x = h0; hh.y = h1;
                    ll.x = __float2bfloat16(v0 - __bfloat162float(h0));
                    ll.y = __float2bfloat16(v1 - __bfloat162float(h1));
                    *reinterpret_cast<__nv_bfloat162*>(&outH[(size_t)r * ldOut + c]) = hh;
                    *reinterpret_cast<__nv_bfloat162*>(&outL[(size_t)r * ldOut + c]) = ll;
                }
            }
        }
    }
}

// ---------------- per-row loss (OUT stride = NPAD2) -----------------------
__global__ __launch_bounds__(256) void loss_kernel(const float* __restrict__ noise) {
    int warp = threadIdx.x >> 5, lane = threadIdx.x & 31;
    int b = blockIdx.x * 8 + warp;
    __shared__ float s_row[8];
    int t = d_TT[b];
    int tm1 = (t > 0) ? t - 1 : 0;
    const float* outp = d_OUT + (size_t)b * NPAD2;

    float g = 0.f;
    if (lane < NNUM) { float d = noise[b * NNUM + lane] - outp[lane]; g = d * d; }

    float kl = 0.f, dec = 0.f;
    if (lane < NCAT) {
        int hot = d_CAT[b * NCAT + lane];
        int sm  = d_SAMP[b * NCAT + lane];
        const float* oc = outp + NNUM + lane * KCLS;
        float v[KCLS];
        float mx = -1e30f;
        #pragma unroll
        for (int k = 0; k < KCLS; k++) { v[k] = oc[k]; mx = fmaxf(mx, v[k]); }
        float se = 0.f;
        #pragma unroll
        for (int k = 0; k < KCLS; k++) se += expf(v[k] - mx);
        float lse = mx + logf(se);

        float PH = laddexp(d_LOG_A[t], d_LOG_1M_A[t] - LOGK_F);
        float PO = laddexp(CL_F + d_LOG_A[t], d_LOG_1M_A[t] - LOGK_F);
        float H1, O1;
        if (t == 0) { H1 = 0.f; O1 = CL_F; }
        else {
            H1 = laddexp(d_LOG_CA[tm1], d_LOG_1M_CA[tm1] - LOGK_F);
            O1 = laddexp(CL_F + d_LOG_CA[tm1], d_LOG_1M_CA[tm1] - LOGK_F);
        }

        float unm[KCLS], unt[KCLS];
        float mmax = -1e30f, tmax = -1e30f;
        #pragma unroll
        for (int k = 0; k < KCLS; k++) {
            float lx0 = v[k] - lse;
            float ev  = (t == 0) ? lx0
                                 : laddexp(lx0 + d_LOG_CA[tm1], d_LOG_1M_CA[tm1] - LOGK_F);
            float pk  = (k == sm) ? PH : PO;
            float um = ev + pk;            unm[k] = um; mmax = fmaxf(mmax, um);
            float ut = ((k == hot) ? H1 : O1) + pk; unt[k] = ut; tmax = fmaxf(tmax, ut);
        }
        float ms = 0.f, ts = 0.f;
        #pragma unroll
        for (int k = 0; k < KCLS; k++) { ms += expf(unm[k] - mmax); ts += expf(unt[k] - tmax); }
        float mlse = mmax + logf(ms), tlse = tmax + logf(ts);
        float EXPL = expf(CL_F);
        #pragma unroll
        for (int k = 0; k < KCLS; k++) {
            float lt = unt[k] - tlse, lm = unm[k] - mlse;
            kl  += expf(lt) * (lt - lm);
            dec -= ((k == hot) ? 1.0f : EXPL) * lm;
        }
    }

    #pragma unroll
    for (int o = 16; o; o >>= 1) {
        g   += __shfl_xor_sync(0xffffffffu, g, o);
        kl  += __shfl_xor_sync(0xffffffffu, kl, o);
        dec += __shfl_xor_sync(0xffffffffu, dec, o);
    }
    if (lane == 0) {
        float Lt = (t == 0) ? dec : kl;
        s_row[warp] = (Lt + d_KLP) * (1.0f / ((float)NCAT * (float)BATCH))
                    + g * (1.0f / ((float)NNUM * (float)BATCH));
    }
    __syncthreads();
    if (threadIdx.x == 0) {
        float s = 0.f;
        #pragma unroll
        for (int i = 0; i < 8; i++) s += s_row[i];
        d_PART[blockIdx.x] = s;
    }
}

__global__ void final_kernel(float* __restrict__ out) {
    __shared__ float s[256];
    float a = 0.f;
    for (int i = threadIdx.x; i < BATCH / 8; i += 256) a += d_PART[i];
    s[threadIdx.x] = a;
    __syncthreads();
    for (int st = 128; st; st >>= 1) {
        if (threadIdx.x < st) s[threadIdx.x] += s[threadIdx.x + st];
        __syncthreads();
    }
    if (threadIdx.x == 0) out[0] = s[0];
}

// ---------------- launch ----------------
extern "C" void kernel_launch(void* const* d_in, const int* in_sizes, int n_in,
                              void* d_out, int out_size) {
    const float* x_num   = (const float*)d_in[0];
    const int*   x_cat_r = (const int*)  d_in[1];
    const int*   t_r     = (const int*)  d_in[2];
    const float* noise   = (const float*)d_in[3];
    const float* gumbel  = (const float*)d_in[4];
    const float* te_w1   = (const float*)d_in[5];
    const float* te_b1   = (const float*)d_in[6];
    const float* te_w2   = (const float*)d_in[7];
    const float* te_b2   = (const float*)d_in[8];
    const float* proj_w  = (const float*)d_in[9];
    const float* proj_b  = (const float*)d_in[10];
    const float* mlp_w1  = (const float*)d_in[11];
    const float* mlp_b1  = (const float*)d_in[12];
    const float* mlp_w2  = (const float*)d_in[13];
    const float* mlp_b2  = (const float*)d_in[14];
    float* out = (float*)d_out;

    cudaFuncSetAttribute(mma_gemm, cudaFuncAttributeMaxDynamicSharedMemorySize, GSMEM_BYTES);
    cudaFuncSetAttribute(build_h_kernel, cudaFuncAttributeMaxDynamicSharedMemorySize, BH_SMEM);

    __nv_bfloat16 *pE0H, *pE0L, *pE1H, *pE1L;
    __nv_bfloat16 *pW1H, *pW1L, *pW2H, *pW2L, *pM1H, *pM1L, *pM2H, *pM2L;
    __nv_bfloat16 *pHH, *pHL, *pUH, *pUL;
    float *pEMB, *pOUT, *pB2;
    cudaGetSymbolAddress((void**)&pE0H, d_E0H); cudaGetSymbolAddress((void**)&pE0L, d_E0L);
    cudaGetSymbolAddress((void**)&pE1H, d_E1H); cudaGetSymbolAddress((void**)&pE1L, d_E1L);
    cudaGetSymbolAddress((void**)&pW1H, d_W1TH); cudaGetSymbolAddress((void**)&pW1L, d_W1TL);
    cudaGetSymbolAddress((void**)&pW2H, d_W2TH); cudaGetSymbolAddress((void**)&pW2L, d_W2TL);
    cudaGetSymbolAddress((void**)&pM1H, d_M1TH); cudaGetSymbolAddress((void**)&pM1L, d_M1TL);
    cudaGetSymbolAddress((void**)&pM2H, d_M2TH); cudaGetSymbolAddress((void**)&pM2L, d_M2TL);
    cudaGetSymbolAddress((void**)&pHH, d_HH); cudaGetSymbolAddress((void**)&pHL, d_HL);
    cudaGetSymbolAddress((void**)&pUH, d_UH); cudaGetSymbolAddress((void**)&pUL, d_UL);
    cudaGetSymbolAddress((void**)&pEMB, d_EMB); cudaGetSymbolAddress((void**)&pOUT, d_OUT);
    cudaGetSymbolAddress((void**)&pB2, d_B2P);

    sched_kernel<<<1, 1024>>>();
    detect_kernel<<<1, 32>>>(t_r, x_cat_r);
    convert_all_kernel<<<(BATCH * NCAT + 255) / 256, 256>>>(t_r, x_cat_r, mlp_b2);
    temb_kernel<<<dim3(TPAD, DIMT / 256), 256>>>();
    transpose_all_kernel<<<3584, dim3(32, 8)>>>(te_w1, te_w2, mlp_w1, mlp_w2);
    sumall_kernel<<<DIMT / 256, 256>>>(proj_w);
    sample_kernel<<<(BATCH * NCAT + 255) / 256, 256>>>(x_num, noise, gumbel);

    // te MLP over 1024 (padded) unique timesteps
    mma_gemm<<<dim3(DIMT / 128, TPAD / 128), 256, GSMEM_BYTES>>>(
        pE0H, pE0L, pW1H, pW1L, te_b1, nullptr, pE1H, pE1L, DIMT, DIMT, /*silu*/2);
    mma_gemm<<<dim3(DIMT / 128, TPAD / 128), 256, GSMEM_BYTES>>>(
        pE1H, pE1L, pW2H, pW2L, te_b2, pEMB, nullptr, nullptr, DIMT, DIMT, /*fp32*/0);

    // proj via sparse one-hot evaluation (fp32 exact) -> hi/lo H
    build_h_kernel<<<dim3(DIMT / 128, BATCH / 128), 256, BH_SMEM>>>(proj_w, proj_b);

    // mlp1: relu -> hi/lo
    mma_gemm<<<dim3(HIDN / 128, BATCH / 128), 256, GSMEM_BYTES>>>(
        pHH, pHL, pM1H, pM1L, mlp_b1, nullptr, pUH, pUL, DIMT, HIDN, /*relu*/1);
    // mlp2: fp32 out (padded to 512)
    mma_gemm<<<dim3(NPAD2 / 128, BATCH / 128), 256, GSMEM_BYTES>>>(
        pUH, pUL, pM2H, pM2L, pB2, pOUT, nullptr, nullptr, HIDN, NPAD2, /*fp32*/0);

    loss_kernel<<<BATCH / 8, 256>>>(noise);
    final_kernel<<<1, 256>>>(out);
}

// round 13
// speedup vs baseline: 1.4349x; 1.4349x over previous
#include <cuda_runtime.h>
#include <cuda_bf16.h>
#include <math.h>
#include <stdint.h>

// ---------------- problem constants ----------------
#define BATCH  16384
#define NNUM   16
#define NCAT   24
#define KCLS   16
#define CATDIM 384
#define DIN    400
#define KPAD   512          // padded DIN for proj GEMM
#define DIMT   1024
#define HIDN   1024
#define NPAD2  512          // padded DIN for mlp2 output
#define TSTEPS 1000
#define TPAD   1024

#define LOGK_F 2.772588722239781f
#define CL_F   (-69.07755278982137f)

// ---------------- device scratch ----------------
__device__ float d_LOG_A[TSTEPS], d_LOG_1M_A[TSTEPS];
__device__ float d_LOG_CA[TSTEPS], d_LOG_1M_CA[TSTEPS];
__device__ float d_SQAC[TSTEPS], d_SQ1MAC[TSTEPS];
__device__ float d_KLP;
__device__ int   d_t64, d_c64;
__device__ int   d_TT[BATCH];
__device__ int   d_CAT[BATCH * NCAT];
__device__ int   d_SAMP[BATCH * NCAT];

__device__ __nv_bfloat16 d_E0H[TPAD * DIMT], d_E0L[TPAD * DIMT];
__device__ __nv_bfloat16 d_E1H[TPAD * DIMT], d_E1L[TPAD * DIMT];
__device__ float         d_EMB[TPAD * DIMT];
__device__ __nv_bfloat16 d_W1TH[DIMT * DIMT], d_W1TL[DIMT * DIMT];   // te_w1^T
__device__ __nv_bfloat16 d_W2TH[DIMT * DIMT], d_W2TL[DIMT * DIMT];   // te_w2^T
__device__ __nv_bfloat16 d_M1TH[HIDN * DIMT], d_M1TL[HIDN * DIMT];   // mlp_w1^T
__device__ __nv_bfloat16 d_M2TH[NPAD2 * HIDN], d_M2TL[NPAD2 * HIDN]; // mlp_w2^T padded
__device__ __nv_bfloat16 d_PJTH[DIMT * KPAD], d_PJTL[DIMT * KPAD];   // proj_w^T padded
__device__ __nv_bfloat16 d_XINH[(size_t)BATCH * KPAD], d_XINL[(size_t)BATCH * KPAD];
__device__ __nv_bfloat16 d_HH[(size_t)BATCH * DIMT], d_HL[(size_t)BATCH * DIMT];
__device__ __nv_bfloat16 d_UH[(size_t)BATCH * DIMT], d_UL[(size_t)BATCH * DIMT];
__device__ float         d_OUT[(size_t)BATCH * NPAD2];
__device__ float         d_B2P[NPAD2];
__device__ float d_PART[BATCH / 8];

// ---------------- helpers ----------------
__device__ __forceinline__ float laddexp(float a, float b) {
    float m = fmaxf(a, b);
    return m + logf(expf(a - m) + expf(b - m));
}
__device__ __forceinline__ uint32_t smem_u32(const void* p) {
    return (uint32_t)__cvta_generic_to_shared(p);
}
#define SWZ128(o) ((o) ^ (((o) >> 3) & 0x70))

__device__ __forceinline__ void ldsm4(uint32_t* r, uint32_t addr) {
    asm volatile("ldmatrix.sync.aligned.m8n8.x4.shared.b16 {%0,%1,%2,%3}, [%4];"
        : "=r"(r[0]), "=r"(r[1]), "=r"(r[2]), "=r"(r[3]) : "r"(addr));
}
__device__ __forceinline__ void mma16816(float* c, const uint32_t* a, uint32_t b0, uint32_t b1) {
    asm volatile("mma.sync.aligned.m16n8k16.row.col.f32.bf16.bf16.f32 "
        "{%0,%1,%2,%3}, {%4,%5,%6,%7}, {%8,%9}, {%0,%1,%2,%3};"
        : "+f"(c[0]), "+f"(c[1]), "+f"(c[2]), "+f"(c[3])
        : "r"(a[0]), "r"(a[1]), "r"(a[2]), "r"(a[3]), "r"(b0), "r"(b1));
}

// ---------------- schedules ----------------
__global__ void sched_kernel() {
    __shared__ double s[1024];
    int i = threadIdx.x;
    const double PI = 3.14159265358979323846;
    double la = 0.0;
    if (i < TSTEPS) {
        double u0 = (double)i / (double)TSTEPS;
        double u1 = (double)(i + 1) / (double)TSTEPS;
        double c0 = cos((u0 + 0.008) / 1.008 * PI / 2.0); double ab0 = c0 * c0;
        double c1 = cos((u1 + 0.008) / 1.008 * PI / 2.0); double ab1 = c1 * c1;
        double beta = 1.0 - ab1 / ab0;
        if (beta > 0.999) beta = 0.999;
        la = log(1.0 - beta);
    }
    s[i] = la;
    __syncthreads();
    #pragma unroll
    for (int off = 1; off < 1024; off <<= 1) {
        double v = (i >= off) ? s[i - off] : 0.0;
        __syncthreads();
        s[i] += v;
        __syncthreads();
    }
    if (i < TSTEPS) {
        double lca = s[i];
        d_LOG_A[i]     = (float)la;
        d_LOG_1M_A[i]  = (float)log(1.0 - exp(la) + 1e-40);
        d_LOG_CA[i]    = (float)lca;
        d_LOG_1M_CA[i] = (float)log(1.0 - exp(lca) + 1e-40);
        double ac = exp(lca);
        d_SQAC[i]   = (float)sqrt(ac);
        d_SQ1MAC[i] = (float)sqrt(1.0 - ac);
    }
    __syncthreads();
    if (i == 0) {
        float lcaT = d_LOG_CA[TSTEPS - 1], l1mT = d_LOG_1M_CA[TSTEPS - 1];
        float hT = laddexp(lcaT, l1mT - LOGK_F);
        float oT = laddexp(CL_F + lcaT, l1mT - LOGK_F);
        d_KLP = (float)NCAT * (expf(hT) * (hT + LOGK_F) + 15.0f * expf(oT) * (oT + LOGK_F));
    }
}

// ---------------- dtype sniff ----------------
__global__ void detect_kernel(const int* __restrict__ traw, const int* __restrict__ craw) {
    if (threadIdx.x != 0) return;
    int z = 1;
    for (int i = 0; i < 64; i++) if (traw[2 * i + 1] != 0) { z = 0; break; }
    d_t64 = z;
    z = 1;
    for (int i = 0; i < 64; i++) if (craw[2 * i + 1] != 0) { z = 0; break; }
    d_c64 = z;
}

// ---------------- transpose helper ----------------
__device__ __forceinline__ void do_transpose(
    const float* __restrict__ in, int R, int C, int Rpad,
    __nv_bfloat16* __restrict__ oh, __nv_bfloat16* __restrict__ ol,
    int bx, int by)
{
    __shared__ float tl[32][33];
    int c0 = bx * 32, r0 = by * 32;
    #pragma unroll
    for (int k = 0; k < 4; k++) {
        int r = r0 + threadIdx.y + k * 8;
        int c = c0 + threadIdx.x;
        float v = (r < R && c < C) ? in[(size_t)r * C + c] : 0.f;
        tl[threadIdx.x][threadIdx.y + k * 8] = v;
    }
    __syncthreads();
    #pragma unroll
    for (int k = 0; k < 4; k++) {
        int c = c0 + threadIdx.y + k * 8;   // out row
        int r = r0 + threadIdx.x;           // out col
        float v = tl[threadIdx.y + k * 8][threadIdx.x];
        __nv_bfloat16 h = __float2bfloat16(v);
        oh[(size_t)c * Rpad + r] = h;
        ol[(size_t)c * Rpad + r] = __float2bfloat16(v - __bfloat162float(h));
    }
}

// ---------------- ONE prep kernel: converts + temb + all transposes -------
// Segments (blockDim 32x8 = 256 thr):
//   [0,1536)          : int convert + bias pad
//   [1536,5632)       : timestep embedding (1024 t x 4 col-blocks)
//   [5632,9728)       : transposes (te_w1 1024 | te_w2 1024 | mlp_w1 1024 |
//                       mlp_w2 512 | proj_w 512)
__global__ void prep_kernel(
    const int* __restrict__ traw, const int* __restrict__ craw,
    const float* __restrict__ b2,
    const float* __restrict__ te_w1, const float* __restrict__ te_w2,
    const float* __restrict__ mlp_w1, const float* __restrict__ mlp_w2,
    const float* __restrict__ proj_w)
{
    int b = blockIdx.x;
    int tid = threadIdx.y * 32 + threadIdx.x;
    if (b < 1536) {
        int i = b * 256 + tid;
        if (i < BATCH) d_TT[i] = d_t64 ? traw[2 * i] : traw[i];
        if (i < BATCH * NCAT) d_CAT[i] = d_c64 ? craw[2 * i] : craw[i];
        if (i < NPAD2) d_B2P[i] = (i < DIN) ? b2[i] : 0.f;
    } else if (b < 5632) {
        int idx = b - 1536;
        int t = idx >> 2;
        int j = (idx & 3) * 256 + tid;
        float v = 0.f;
        if (t < TSTEPS) {
            int h = j & 511;
            float freq = expf(-9.210340371976184f * (float)h / 512.0f);
            float arg = (float)t * freq;
            v = (j < 512) ? cosf(arg) : sinf(arg);
        }
        __nv_bfloat16 hi = __float2bfloat16(v);
        __nv_bfloat16 lo = __float2bfloat16(v - __bfloat162float(hi));
        d_E0H[t * DIMT + j] = hi;
        d_E0L[t * DIMT + j] = lo;
    } else {
        b -= 5632;
        if (b < 1024) {
            do_transpose(te_w1, DIMT, DIMT, DIMT, d_W1TH, d_W1TL, b & 31, b >> 5);
        } else if (b < 2048) {
            b -= 1024;
            do_transpose(te_w2, DIMT, DIMT, DIMT, d_W2TH, d_W2TL, b & 31, b >> 5);
        } else if (b < 3072) {
            b -= 2048;
            do_transpose(mlp_w1, DIMT, HIDN, DIMT, d_M1TH, d_M1TL, b & 31, b >> 5);
        } else if (b < 3584) {
            b -= 3072;                               // 16 x 32 blocks
            do_transpose(mlp_w2, HIDN, DIN, HIDN, d_M2TH, d_M2TL, b & 15, b >> 4);
        } else {
            b -= 3584;                               // 32 x 16 blocks
            do_transpose(proj_w, DIN, DIMT, KPAD, d_PJTH, d_PJTL, b & 31, b >> 5);
        }
    }
}

// ---------------- build x_in (hi/lo bf16, padded to 512) + sampling -------
__global__ __launch_bounds__(128) void build_xin_kernel(
    const float* __restrict__ x_num, const float* __restrict__ noise,
    const float* __restrict__ gumbel) {
    int b = blockIdx.x;
    int tid = threadIdx.x;
    __shared__ float s_x[NNUM];
    __shared__ int   s_s[NCAT];
    int t = d_TT[b];

    if (tid < NNUM)
        s_x[tid] = d_SQAC[t] * x_num[b * NNUM + tid] + d_SQ1MAC[t] * noise[b * NNUM + tid];
    if (tid < NCAT) {
        int hot = d_CAT[b * NCAT + tid];
        float hv = laddexp(d_LOG_CA[t], d_LOG_1M_CA[t] - LOGK_F);
        float ov = laddexp(CL_F + d_LOG_CA[t], d_LOG_1M_CA[t] - LOGK_F);
        const float* gp = gumbel + (size_t)b * CATDIM + tid * KCLS;
        float best = -1e30f; int bi = 0;
        #pragma unroll
        for (int k = 0; k < KCLS; k++) {
            float g = -logf(-logf(gp[k] + 1e-30f) + 1e-30f);
            float v = g + ((k == hot) ? hv : ov);
            if (v > best) { best = v; bi = k; }
        }
        s_s[tid] = bi;
        d_SAMP[b * NCAT + tid] = bi;
    }
    __syncthreads();

    const __nv_bfloat16 clh = __float2bfloat16(CL_F);
    const __nv_bfloat16 cll = __float2bfloat16(CL_F - __bfloat162float(clh));
    #pragma unroll
    for (int rr = 0; rr < KPAD / 128; rr++) {
        int j = tid + rr * 128;
        __nv_bfloat16 h, l;
        if (j < NNUM) {
            float v = s_x[j];
            h = __float2bfloat16(v);
            l = __float2bfloat16(v - __bfloat162float(h));
        } else if (j < DIN) {
            int c = (j - NNUM) >> 4, k = (j - NNUM) & 15;
            if (k == s_s[c]) { h = __float2bfloat16(0.f); l = h; }
            else { h = clh; l = cll; }
        } else {
            h = __float2bfloat16(0.f); l = h;
        }
        d_XINH[(size_t)b * KPAD + j] = h;
        d_XINL[(size_t)b * KPAD + j] = l;
    }
}

// ---------------- fused 3-term bf16 mma.sync GEMM, 3-stage pipeline -------
// D = Ahi@Bhi^T + Ahi@Blo^T + Alo@Bhi^T + bias.  4 tiles loaded once per
// 64-wide k-block; 3-stage cp.async (prefetch depth 2); ONE sync per slab.
// mode 0: fp32 out   1: relu->hi/lo   2: silu->hi/lo   3: +emb[t[row]]->hi/lo
#define GSMEM_BYTES 196608
__global__ __launch_bounds__(256) void mma_gemm(
    const __nv_bfloat16* __restrict__ Ahi, const __nv_bfloat16* __restrict__ Alo,
    const __nv_bfloat16* __restrict__ Bhi, const __nv_bfloat16* __restrict__ Blo,
    const float* __restrict__ bias,
    float* __restrict__ outF, __nv_bfloat16* __restrict__ outH, __nv_bfloat16* __restrict__ outL,
    const float* __restrict__ emb,
    int Kelem, int ldOut, int mode)
{
    extern __shared__ char smem[];
    const uint32_t sbase = smem_u32(smem);      // 3 stages x 64KB: Ahi|Alo|Bhi|Blo
    int tid = threadIdx.x, wid = tid >> 5, lane = tid & 31;
    int wm = (wid & 3) * 32, wn = (wid >> 2) * 64;
    int rowBase = blockIdx.y * 128, colBase = blockIdx.x * 128;

    int KS = Kelem >> 6;

    int c0i = tid * 4;
    int ldRow = c0i >> 3;
    int ldUn  = c0i & 7;

    float acc[2][8][4];
    #pragma unroll
    for (int a = 0; a < 2; a++)
        #pragma unroll
        for (int b = 0; b < 8; b++)
            #pragma unroll
            for (int c = 0; c < 4; c++) acc[a][b][c] = 0.f;

    auto issue = [&](int s) {
        int kb = s << 6;
        int st = s % 3;
        const __nv_bfloat16* gaH = Ahi + (size_t)(rowBase + ldRow) * Kelem + kb + ldUn * 8;
        const __nv_bfloat16* gaL = Alo + (size_t)(rowBase + ldRow) * Kelem + kb + ldUn * 8;
        const __nv_bfloat16* gbH = Bhi + (size_t)(colBase + ldRow) * Kelem + kb + ldUn * 8;
        const __nv_bfloat16* gbL = Blo + (size_t)(colBase + ldRow) * Kelem + kb + ldUn * 8;
        uint32_t base = sbase + st * 65536;
        #pragma unroll
        for (int q = 0; q < 4; q++) {
            uint32_t off = SWZ128(ldRow * 128 + (ldUn + q) * 16);
            asm volatile("cp.async.cg.shared.global [%0], [%1], 16;" :: "r"(base + off),         "l"(gaH + q * 8));
            asm volatile("cp.async.cg.shared.global [%0], [%1], 16;" :: "r"(base + 16384 + off), "l"(gaL + q * 8));
            asm volatile("cp.async.cg.shared.global [%0], [%1], 16;" :: "r"(base + 32768 + off), "l"(gbH + q * 8));
            asm volatile("cp.async.cg.shared.global [%0], [%1], 16;" :: "r"(base + 49152 + off), "l"(gbL + q * 8));
        }
    };

    issue(0);
    asm volatile("cp.async.commit_group;\n" ::: "memory");
    if (KS > 1) issue(1);
    asm volatile("cp.async.commit_group;\n" ::: "memory");

    int aRowC = wm + (lane & 15);
    int aKC   = (lane & 16);
    int bRowC = wn + (lane & 7) + ((lane & 16) >> 1);
    int bKC   = (lane & 8) * 2;

    for (int s = 0; s < KS; s++) {
        asm volatile("cp.async.wait_group 1;\n" ::: "memory");
        __syncthreads();

        if (s + 2 < KS) issue(s + 2);
        asm volatile("cp.async.commit_group;\n" ::: "memory");

        uint32_t base = sbase + (s % 3) * 65536;
        uint32_t baAH = base, baAL = base + 16384, baBH = base + 32768, baBL = base + 49152;
        #pragma unroll
        for (int kk = 0; kk < 4; kk++) {
            uint32_t aH[2][4], aL[2][4], bH[4][4], bL[4][4];
            #pragma unroll
            for (int mi = 0; mi < 2; mi++) {
                uint32_t off = SWZ128((aRowC + mi * 16) * 128 + kk * 32 + aKC);
                ldsm4(aH[mi], baAH + off);
                ldsm4(aL[mi], baAL + off);
            }
            #pragma unroll
            for (int nt = 0; nt < 4; nt++) {
                uint32_t off = SWZ128((bRowC + nt * 16) * 128 + kk * 32 + bKC);
                ldsm4(bH[nt], baBH + off);
                ldsm4(bL[nt], baBL + off);
            }
            #pragma unroll
            for (int mi = 0; mi < 2; mi++)
                #pragma unroll
                for (int nt = 0; nt < 4; nt++) {
                    mma16816(acc[mi][nt * 2],     aH[mi], bH[nt][0], bH[nt][1]);
                    mma16816(acc[mi][nt * 2 + 1], aH[mi], bH[nt][2], bH[nt][3]);
                }
            #pragma unroll
            for (int mi = 0; mi < 2; mi++)
                #pragma unroll
                for (int nt = 0; nt < 4; nt++) {
                    mma16816(acc[mi][nt * 2],     aH[mi], bL[nt][0], bL[nt][1]);
                    mma16816(acc[mi][nt * 2 + 1], aH[mi], bL[nt][2], bL[nt][3]);
                }
            #pragma unroll
            for (int mi = 0; mi < 2; mi++)
                #pragma unroll
                for (int nt = 0; nt < 4; nt++) {
                    mma16816(acc[mi][nt * 2],     aL[mi], bH[nt][0], bH[nt][1]);
                    mma16816(acc[mi][nt * 2 + 1], aL[mi], bH[nt][2], bH[nt][3]);
                }
        }
    }

    // ---------------- epilogue ----------------
    #pragma unroll
    for (int mi = 0; mi < 2; mi++) {
        #pragma unroll
        for (int half = 0; half < 2; half++) {
            int r = rowBase + wm + mi * 16 + (lane >> 2) + half * 8;
            int tE = (mode == 3) ? d_TT[r] : 0;
            #pragma unroll
            for (int ni = 0; ni < 8; ni++) {
                int c = colBase + wn + ni * 8 + (lane & 3) * 2;
                float v0 = acc[mi][ni][half * 2 + 0] + bias[c];
                float v1 = acc[mi][ni][half * 2 + 1] + bias[c + 1];
                if (mode == 0) {
                    float2 v; v.x = v0; v.y = v1;
                    *reinterpret_cast<float2*>(&outF[(size_t)r * ldOut + c]) = v;
                } else {
                    if (mode == 1) {
                        v0 = fmaxf(v0, 0.f); v1 = fmaxf(v1, 0.f);
                    } else if (mode == 2) {
                        v0 = v0 / (1.f + expf(-v0)); v1 = v1 / (1.f + expf(-v1));
                    } else {
                        v0 += emb[(size_t)tE * DIMT + c];
                        v1 += emb[(size_t)tE * DIMT + c + 1];
                    }
                    __nv_bfloat16 h0 = __float2bfloat16(v0), h1 = __float2bfloat16(v1);
                    __nv_bfloat162 hh, ll;
                    hh.x = h0; hh.y = h1;
                    ll.x = __float2bfloat16(v0 - __bfloat162float(h0));
                    ll.y = __float2bfloat16(v1 - __bfloat162float(h1));
                    *reinterpret_cast<__nv_bfloat162*>(&outH[(size_t)r * ldOut + c]) = hh;
                    *reinterpret_cast<__nv_bfloat162*>(&outL[(size_t)r * ldOut + c]) = ll;
                }
            }
        }
    }
}

// ---------------- per-row loss (OUT stride = NPAD2) -----------------------
__global__ __launch_bounds__(256) void loss_kernel(const float* __restrict__ noise) {
    int warp = threadIdx.x >> 5, lane = threadIdx.x & 31;
    int b = blockIdx.x * 8 + warp;
    __shared__ float s_row[8];
    int t = d_TT[b];
    int tm1 = (t > 0) ? t - 1 : 0;
    const float* outp = d_OUT + (size_t)b * NPAD2;

    float g = 0.f;
    if (lane < NNUM) { float d = noise[b * NNUM + lane] - outp[lane]; g = d * d; }

    float kl = 0.f, dec = 0.f;
    if (lane < NCAT) {
        int hot = d_CAT[b * NCAT + lane];
        int sm  = d_SAMP[b * NCAT + lane];
        const float* oc = outp + NNUM + lane * KCLS;
        float v[KCLS];
        float mx = -1e30f;
        #pragma unroll
        for (int k = 0; k < KCLS; k++) { v[k] = oc[k]; mx = fmaxf(mx, v[k]); }
        float se = 0.f;
        #pragma unroll
        for (int k = 0; k < KCLS; k++) se += expf(v[k] - mx);
        float lse = mx + logf(se);

        float PH = laddexp(d_LOG_A[t], d_LOG_1M_A[t] - LOGK_F);
        float PO = laddexp(CL_F + d_LOG_A[t], d_LOG_1M_A[t] - LOGK_F);
        float H1, O1;
        if (t == 0) { H1 = 0.f; O1 = CL_F; }
        else {
            H1 = laddexp(d_LOG_CA[tm1], d_LOG_1M_CA[tm1] - LOGK_F);
            O1 = laddexp(CL_F + d_LOG_CA[tm1], d_LOG_1M_CA[tm1] - LOGK_F);
        }

        float unm[KCLS], unt[KCLS];
        float mmax = -1e30f, tmax = -1e30f;
        #pragma unroll
        for (int k = 0; k < KCLS; k++) {
            float lx0 = v[k] - lse;
            float ev  = (t == 0) ? lx0
                                 : laddexp(lx0 + d_LOG_CA[tm1], d_LOG_1M_CA[tm1] - LOGK_F);
            float pk  = (k == sm) ? PH : PO;
            float um = ev + pk;            unm[k] = um; mmax = fmaxf(mmax, um);
            float ut = ((k == hot) ? H1 : O1) + pk; unt[k] = ut; tmax = fmaxf(tmax, ut);
        }
        float ms = 0.f, ts = 0.f;
        #pragma unroll
        for (int k = 0; k < KCLS; k++) { ms += expf(unm[k] - mmax); ts += expf(unt[k] - tmax); }
        float mlse = mmax + logf(ms), tlse = tmax + logf(ts);
        float EXPL = expf(CL_F);
        #pragma unroll
        for (int k = 0; k < KCLS; k++) {
            float lt = unt[k] - tlse, lm = unm[k] - mlse;
            kl  += expf(lt) * (lt - lm);
            dec -= ((k == hot) ? 1.0f : EXPL) * lm;
        }
    }

    #pragma unroll
    for (int o = 16; o; o >>= 1) {
        g   += __shfl_xor_sync(0xffffffffu, g, o);
        kl  += __shfl_xor_sync(0xffffffffu, kl, o);
        dec += __shfl_xor_sync(0xffffffffu, dec, o);
    }
    if (lane == 0) {
        float Lt = (t == 0) ? dec : kl;
        s_row[warp] = (Lt + d_KLP) * (1.0f / ((float)NCAT * (float)BATCH))
                    + g * (1.0f / ((float)NNUM * (float)BATCH));
    }
    __syncthreads();
    if (threadIdx.x == 0) {
        float s = 0.f;
        #pragma unroll
        for (int i = 0; i < 8; i++) s += s_row[i];
        d_PART[blockIdx.x] = s;
    }
}

__global__ void final_kernel(float* __restrict__ out) {
    __shared__ float s[256];
    float a = 0.f;
    for (int i = threadIdx.x; i < BATCH / 8; i += 256) a += d_PART[i];
    s[threadIdx.x] = a;
    __syncthreads();
    for (int st = 128; st; st >>= 1) {
        if (threadIdx.x < st) s[threadIdx.x] += s[threadIdx.x + st];
        __syncthreads();
    }
    if (threadIdx.x == 0) out[0] = s[0];
}

// ---------------- launch ----------------
extern "C" void kernel_launch(void* const* d_in, const int* in_sizes, int n_in,
                              void* d_out, int out_size) {
    const float* x_num   = (const float*)d_in[0];
    const int*   x_cat_r = (const int*)  d_in[1];
    const int*   t_r     = (const int*)  d_in[2];
    const float* noise   = (const float*)d_in[3];
    const float* gumbel  = (const float*)d_in[4];
    const float* te_w1   = (const float*)d_in[5];
    const float* te_b1   = (const float*)d_in[6];
    const float* te_w2   = (const float*)d_in[7];
    const float* te_b2   = (const float*)d_in[8];
    const float* proj_w  = (const float*)d_in[9];
    const float* proj_b  = (const float*)d_in[10];
    const float* mlp_w1  = (const float*)d_in[11];
    const float* mlp_b1  = (const float*)d_in[12];
    const float* mlp_w2  = (const float*)d_in[13];
    const float* mlp_b2  = (const float*)d_in[14];
    float* out = (float*)d_out;

    cudaFuncSetAttribute(mma_gemm, cudaFuncAttributeMaxDynamicSharedMemorySize, GSMEM_BYTES);

    __nv_bfloat16 *pE0H, *pE0L, *pE1H, *pE1L;
    __nv_bfloat16 *pW1H, *pW1L, *pW2H, *pW2L, *pM1H, *pM1L, *pM2H, *pM2L, *pPJH, *pPJL;
    __nv_bfloat16 *pXIH, *pXIL, *pHH, *pHL, *pUH, *pUL;
    float *pEMB, *pOUT, *pB2;
    cudaGetSymbolAddress((void**)&pE0H, d_E0H); cudaGetSymbolAddress((void**)&pE0L, d_E0L);
    cudaGetSymbolAddress((void**)&pE1H, d_E1H); cudaGetSymbolAddress((void**)&pE1L, d_E1L);
    cudaGetSymbolAddress((void**)&pW1H, d_W1TH); cudaGetSymbolAddress((void**)&pW1L, d_W1TL);
    cudaGetSymbolAddress((void**)&pW2H, d_W2TH); cudaGetSymbolAddress((void**)&pW2L, d_W2TL);
    cudaGetSymbolAddress((void**)&pM1H, d_M1TH); cudaGetSymbolAddress((void**)&pM1L, d_M1TL);
    cudaGetSymbolAddress((void**)&pM2H, d_M2TH); cudaGetSymbolAddress((void**)&pM2L, d_M2TL);
    cudaGetSymbolAddress((void**)&pPJH, d_PJTH); cudaGetSymbolAddress((void**)&pPJL, d_PJTL);
    cudaGetSymbolAddress((void**)&pXIH, d_XINH); cudaGetSymbolAddress((void**)&pXIL, d_XINL);
    cudaGetSymbolAddress((void**)&pHH, d_HH); cudaGetSymbolAddress((void**)&pHL, d_HL);
    cudaGetSymbolAddress((void**)&pUH, d_UH); cudaGetSymbolAddress((void**)&pUL, d_UL);
    cudaGetSymbolAddress((void**)&pEMB, d_EMB); cudaGetSymbolAddress((void**)&pOUT, d_OUT);
    cudaGetSymbolAddress((void**)&pB2, d_B2P);

    sched_kernel<<<1, 1024>>>();                                      // our 1
    detect_kernel<<<1, 32>>>(t_r, x_cat_r);                           // our 2
    prep_kernel<<<9728, dim3(32, 8)>>>(t_r, x_cat_r, mlp_b2,
                                       te_w1, te_w2, mlp_w1, mlp_w2, proj_w); // our 3

    // te MLP over 1024 (padded) unique timesteps  — our 4: ncu-profiled launch
    mma_gemm<<<dim3(DIMT / 128, TPAD / 128), 256, GSMEM_BYTES>>>(
        pE0H, pE0L, pW1H, pW1L, te_b1, nullptr, pE1H, pE1L, nullptr, DIMT, DIMT, /*silu*/2);
    mma_gemm<<<dim3(DIMT / 128, TPAD / 128), 256, GSMEM_BYTES>>>(
        pE1H, pE1L, pW2H, pW2L, te_b2, pEMB, nullptr, nullptr, nullptr, DIMT, DIMT, /*fp32*/0);

    build_xin_kernel<<<BATCH, 128>>>(x_num, noise, gumbel);

    // proj: h = x_in@proj_w + proj_b + emb[t]   -> hi/lo
    mma_gemm<<<dim3(DIMT / 128, BATCH / 128), 256, GSMEM_BYTES>>>(
        pXIH, pXIL, pPJH, pPJL, proj_b, nullptr, pHH, pHL, pEMB, KPAD, DIMT, /*emb*/3);
    // mlp1: relu -> hi/lo
    mma_gemm<<<dim3(HIDN / 128, BATCH / 128), 256, GSMEM_BYTES>>>(
        pHH, pHL, pM1H, pM1L, mlp_b1, nullptr, pUH, pUL, nullptr, DIMT, HIDN, /*relu*/1);
    // mlp2: fp32 out (padded to 512)
    mma_gemm<<<dim3(NPAD2 / 128, BATCH / 128), 256, GSMEM_BYTES>>>(
        pUH, pUL, pM2H, pM2L, pB2, pOUT, nullptr, nullptr, nullptr, HIDN, NPAD2, /*fp32*/0);

    loss_kernel<<<BATCH / 8, 256>>>(noise);
    final_kernel<<<1, 256>>>(out);
}

// round 16
// speedup vs baseline: 1.6270x; 1.1339x over previous
#include <cuda_runtime.h>
#include <cuda_bf16.h>
#include <math.h>
#include <stdint.h>

// ---------------- problem constants ----------------
#define BATCH  16384
#define NNUM   16
#define NCAT   24
#define KCLS   16
#define CATDIM 384
#define DIN    400
#define KPAD   512          // padded DIN for proj GEMM
#define DIMT   1024
#define HIDN   1024
#define NPAD2  512          // padded DIN for mlp2 output
#define TSTEPS 1000
#define TPAD   1024

#define LOGK_F 2.772588722239781f
#define CL_F   (-69.07755278982137f)

// ---------------- device scratch ----------------
__device__ float d_LOG_A[TSTEPS], d_LOG_1M_A[TSTEPS];
__device__ float d_LOG_CA[TSTEPS], d_LOG_1M_CA[TSTEPS];
__device__ float d_SQAC[TSTEPS], d_SQ1MAC[TSTEPS];
__device__ float d_KLP;
__device__ int   d_t64, d_c64;
__device__ int   d_TT[BATCH];
__device__ int   d_CAT[BATCH * NCAT];
__device__ int   d_SAMP[BATCH * NCAT];

__device__ __nv_bfloat16 d_E0H[TPAD * DIMT], d_E0L[TPAD * DIMT];
__device__ __nv_bfloat16 d_E1H[TPAD * DIMT], d_E1L[TPAD * DIMT];
__device__ float         d_EMB[TPAD * DIMT];
__device__ __nv_bfloat16 d_W1TH[DIMT * DIMT], d_W1TL[DIMT * DIMT];   // te_w1^T
__device__ __nv_bfloat16 d_W2TH[DIMT * DIMT], d_W2TL[DIMT * DIMT];   // te_w2^T
__device__ __nv_bfloat16 d_M1TH[HIDN * DIMT], d_M1TL[HIDN * DIMT];   // mlp_w1^T
__device__ __nv_bfloat16 d_M2TH[NPAD2 * HIDN], d_M2TL[NPAD2 * HIDN]; // mlp_w2^T padded
__device__ __nv_bfloat16 d_PJTH[DIMT * KPAD], d_PJTL[DIMT * KPAD];   // proj_w^T padded
__device__ __nv_bfloat16 d_XINH[(size_t)BATCH * KPAD], d_XINL[(size_t)BATCH * KPAD];
__device__ __nv_bfloat16 d_HH[(size_t)BATCH * DIMT], d_HL[(size_t)BATCH * DIMT];
__device__ __nv_bfloat16 d_UH[(size_t)BATCH * DIMT], d_UL[(size_t)BATCH * DIMT];
__device__ float         d_OUT[(size_t)BATCH * NPAD2];
__device__ float         d_B2P[NPAD2];
__device__ float d_PART[BATCH / 8];

// ---------------- helpers ----------------
__device__ __forceinline__ float laddexp(float a, float b) {
    float m = fmaxf(a, b);
    return m + logf(expf(a - m) + expf(b - m));
}
__device__ __forceinline__ uint32_t smem_u32(const void* p) {
    return (uint32_t)__cvta_generic_to_shared(p);
}
#define SWZ128(o) ((o) ^ (((o) >> 3) & 0x70))
// 64B-row tile swizzle: conflict-free for 8-row ldmatrix groups
#define SWZ64(row, chunk) ((uint32_t)((row) * 64 + ((((chunk) ^ (((row) >> 1) & 3))) << 4)))

__device__ __forceinline__ void ldsm4(uint32_t* r, uint32_t addr) {
    asm volatile("ldmatrix.sync.aligned.m8n8.x4.shared.b16 {%0,%1,%2,%3}, [%4];"
        : "=r"(r[0]), "=r"(r[1]), "=r"(r[2]), "=r"(r[3]) : "r"(addr));
}
__device__ __forceinline__ void mma16816(float* c, const uint32_t* a, uint32_t b0, uint32_t b1) {
    asm volatile("mma.sync.aligned.m16n8k16.row.col.f32.bf16.bf16.f32 "
        "{%0,%1,%2,%3}, {%4,%5,%6,%7}, {%8,%9}, {%0,%1,%2,%3};"
        : "+f"(c[0]), "+f"(c[1]), "+f"(c[2]), "+f"(c[3])
        : "r"(a[0]), "r"(a[1]), "r"(a[2]), "r"(a[3]), "r"(b0), "r"(b1));
}

// ---------------- schedules ----------------
__global__ void sched_kernel() {
    __shared__ double s[1024];
    int i = threadIdx.x;
    const double PI = 3.14159265358979323846;
    double la = 0.0;
    if (i < TSTEPS) {
        double u0 = (double)i / (double)TSTEPS;
        double u1 = (double)(i + 1) / (double)TSTEPS;
        double c0 = cos((u0 + 0.008) / 1.008 * PI / 2.0); double ab0 = c0 * c0;
        double c1 = cos((u1 + 0.008) / 1.008 * PI / 2.0); double ab1 = c1 * c1;
        double beta = 1.0 - ab1 / ab0;
        if (beta > 0.999) beta = 0.999;
        la = log(1.0 - beta);
    }
    s[i] = la;
    __syncthreads();
    #pragma unroll
    for (int off = 1; off < 1024; off <<= 1) {
        double v = (i >= off) ? s[i - off] : 0.0;
        __syncthreads();
        s[i] += v;
        __syncthreads();
    }
    if (i < TSTEPS) {
        double lca = s[i];
        d_LOG_A[i]     = (float)la;
        d_LOG_1M_A[i]  = (float)log(1.0 - exp(la) + 1e-40);
        d_LOG_CA[i]    = (float)lca;
        d_LOG_1M_CA[i] = (float)log(1.0 - exp(lca) + 1e-40);
        double ac = exp(lca);
        d_SQAC[i]   = (float)sqrt(ac);
        d_SQ1MAC[i] = (float)sqrt(1.0 - ac);
    }
    __syncthreads();
    if (i == 0) {
        float lcaT = d_LOG_CA[TSTEPS - 1], l1mT = d_LOG_1M_CA[TSTEPS - 1];
        float hT = laddexp(lcaT, l1mT - LOGK_F);
        float oT = laddexp(CL_F + lcaT, l1mT - LOGK_F);
        d_KLP = (float)NCAT * (expf(hT) * (hT + LOGK_F) + 15.0f * expf(oT) * (oT + LOGK_F));
    }
}

// ---------------- dtype sniff ----------------
__global__ void detect_kernel(const int* __restrict__ traw, const int* __restrict__ craw) {
    if (threadIdx.x != 0) return;
    int z = 1;
    for (int i = 0; i < 64; i++) if (traw[2 * i + 1] != 0) { z = 0; break; }
    d_t64 = z;
    z = 1;
    for (int i = 0; i < 64; i++) if (craw[2 * i + 1] != 0) { z = 0; break; }
    d_c64 = z;
}

// ---------------- transpose helper ----------------
__device__ __forceinline__ void do_transpose(
    const float* __restrict__ in, int R, int C, int Rpad,
    __nv_bfloat16* __restrict__ oh, __nv_bfloat16* __restrict__ ol,
    int bx, int by)
{
    __shared__ float tl[32][33];
    int c0 = bx * 32, r0 = by * 32;
    #pragma unroll
    for (int k = 0; k < 4; k++) {
        int r = r0 + threadIdx.y + k * 8;
        int c = c0 + threadIdx.x;
        float v = (r < R && c < C) ? in[(size_t)r * C + c] : 0.f;
        tl[threadIdx.x][threadIdx.y + k * 8] = v;
    }
    __syncthreads();
    #pragma unroll
    for (int k = 0; k < 4; k++) {
        int c = c0 + threadIdx.y + k * 8;   // out row
        int r = r0 + threadIdx.x;           // out col
        float v = tl[threadIdx.y + k * 8][threadIdx.x];
        __nv_bfloat16 h = __float2bfloat16(v);
        oh[(size_t)c * Rpad + r] = h;
        ol[(size_t)c * Rpad + r] = __float2bfloat16(v - __bfloat162float(h));
    }
}

// ---------------- ONE prep kernel: converts + temb + all transposes -------
__global__ void prep_kernel(
    const int* __restrict__ traw, const int* __restrict__ craw,
    const float* __restrict__ b2,
    const float* __restrict__ te_w1, const float* __restrict__ te_w2,
    const float* __restrict__ mlp_w1, const float* __restrict__ mlp_w2,
    const float* __restrict__ proj_w)
{
    int b = blockIdx.x;
    int tid = threadIdx.y * 32 + threadIdx.x;
    if (b < 1536) {
        int i = b * 256 + tid;
        if (i < BATCH) d_TT[i] = d_t64 ? traw[2 * i] : traw[i];
        if (i < BATCH * NCAT) d_CAT[i] = d_c64 ? craw[2 * i] : craw[i];
        if (i < NPAD2) d_B2P[i] = (i < DIN) ? b2[i] : 0.f;
    } else if (b < 5632) {
        int idx = b - 1536;
        int t = idx >> 2;
        int j = (idx & 3) * 256 + tid;
        float v = 0.f;
        if (t < TSTEPS) {
            int h = j & 511;
            float freq = expf(-9.210340371976184f * (float)h / 512.0f);
            float arg = (float)t * freq;
            v = (j < 512) ? cosf(arg) : sinf(arg);
        }
        __nv_bfloat16 hi = __float2bfloat16(v);
        __nv_bfloat16 lo = __float2bfloat16(v - __bfloat162float(hi));
        d_E0H[t * DIMT + j] = hi;
        d_E0L[t * DIMT + j] = lo;
    } else {
        b -= 5632;
        if (b < 1024) {
            do_transpose(te_w1, DIMT, DIMT, DIMT, d_W1TH, d_W1TL, b & 31, b >> 5);
        } else if (b < 2048) {
            b -= 1024;
            do_transpose(te_w2, DIMT, DIMT, DIMT, d_W2TH, d_W2TL, b & 31, b >> 5);
        } else if (b < 3072) {
            b -= 2048;
            do_transpose(mlp_w1, DIMT, HIDN, DIMT, d_M1TH, d_M1TL, b & 31, b >> 5);
        } else if (b < 3584) {
            b -= 3072;                               // 16 x 32 blocks
            do_transpose(mlp_w2, HIDN, DIN, HIDN, d_M2TH, d_M2TL, b & 15, b >> 4);
        } else {
            b -= 3584;                               // 32 x 16 blocks
            do_transpose(proj_w, DIN, DIMT, KPAD, d_PJTH, d_PJTL, b & 31, b >> 5);
        }
    }
}

// ---------------- build x_in (hi/lo bf16, padded to 512) + sampling -------
__global__ __launch_bounds__(128) void build_xin_kernel(
    const float* __restrict__ x_num, const float* __restrict__ noise,
    const float* __restrict__ gumbel) {
    int b = blockIdx.x;
    int tid = threadIdx.x;
    __shared__ float s_x[NNUM];
    __shared__ int   s_s[NCAT];
    int t = d_TT[b];

    if (tid < NNUM)
        s_x[tid] = d_SQAC[t] * x_num[b * NNUM + tid] + d_SQ1MAC[t] * noise[b * NNUM + tid];
    if (tid < NCAT) {
        int hot = d_CAT[b * NCAT + tid];
        float hv = laddexp(d_LOG_CA[t], d_LOG_1M_CA[t] - LOGK_F);
        float ov = laddexp(CL_F + d_LOG_CA[t], d_LOG_1M_CA[t] - LOGK_F);
        const float* gp = gumbel + (size_t)b * CATDIM + tid * KCLS;
        float best = -1e30f; int bi = 0;
        #pragma unroll
        for (int k = 0; k < KCLS; k++) {
            float g = -logf(-logf(gp[k] + 1e-30f) + 1e-30f);
            float v = g + ((k == hot) ? hv : ov);
            if (v > best) { best = v; bi = k; }
        }
        s_s[tid] = bi;
        d_SAMP[b * NCAT + tid] = bi;
    }
    __syncthreads();

    const __nv_bfloat16 clh = __float2bfloat16(CL_F);
    const __nv_bfloat16 cll = __float2bfloat16(CL_F - __bfloat162float(clh));
    #pragma unroll
    for (int rr = 0; rr < KPAD / 128; rr++) {
        int j = tid + rr * 128;
        __nv_bfloat16 h, l;
        if (j < NNUM) {
            float v = s_x[j];
            h = __float2bfloat16(v);
            l = __float2bfloat16(v - __bfloat162float(h));
        } else if (j < DIN) {
            int c = (j - NNUM) >> 4, k = (j - NNUM) & 15;
            if (k == s_s[c]) { h = __float2bfloat16(0.f); l = h; }
            else { h = clh; l = cll; }
        } else {
            h = __float2bfloat16(0.f); l = h;
        }
        d_XINH[(size_t)b * KPAD + j] = h;
        d_XINL[(size_t)b * KPAD + j] = l;
    }
}

// ---------------- fused 3-term bf16 mma.sync GEMM ------------------------
// BK=32 (64B rows), 3-stage cp.async, 96KB smem -> 2 CTAs/SM (occupancy fix).
// Per kk: AhiBhi, AloBhi, then Blo loaded over dead regs, AhiBlo.
// mode 0: fp32 out   1: relu->hi/lo   2: silu->hi/lo   3: +emb[t[row]]->hi/lo
#define GSMEM_BYTES 98304
#define TILE_B 8192
__global__ __launch_bounds__(256, 2) void mma_gemm(
    const __nv_bfloat16* __restrict__ Ahi, const __nv_bfloat16* __restrict__ Alo,
    const __nv_bfloat16* __restrict__ Bhi, const __nv_bfloat16* __restrict__ Blo,
    const float* __restrict__ bias,
    float* __restrict__ outF, __nv_bfloat16* __restrict__ outH, __nv_bfloat16* __restrict__ outL,
    const float* __restrict__ emb,
    int Kelem, int ldOut, int mode)
{
    extern __shared__ char smem[];
    const uint32_t sbase = smem_u32(smem);      // 3 stages x 32KB: Ahi|Alo|Bhi|Blo (8KB each)
    int tid = threadIdx.x, wid = tid >> 5, lane = tid & 31;
    int wm = (wid & 3) * 32, wn = (wid >> 2) * 64;
    int rowBase = blockIdx.y * 128, colBase = blockIdx.x * 128;

    int KS = Kelem >> 5;                         // 32-wide k-blocks

    // cp.async mapping: per tile 512 16B-chunks / 256 thr = 2 chunks
    int c0 = tid * 2;
    int ldRow = c0 >> 2;          // 0..127
    int ldJ   = c0 & 3;           // starting chunk (0 or 2)

    float acc[2][8][4];
    #pragma unroll
    for (int a = 0; a < 2; a++)
        #pragma unroll
        for (int b = 0; b < 8; b++)
            #pragma unroll
            for (int c = 0; c < 4; c++) acc[a][b][c] = 0.f;

    auto issue = [&](int s) {
        int kb = s << 5;
        uint32_t base = sbase + (s % 3) * 32768;
        const __nv_bfloat16* gaH = Ahi + (size_t)(rowBase + ldRow) * Kelem + kb;
        const __nv_bfloat16* gaL = Alo + (size_t)(rowBase + ldRow) * Kelem + kb;
        const __nv_bfloat16* gbH = Bhi + (size_t)(colBase + ldRow) * Kelem + kb;
        const __nv_bfloat16* gbL = Blo + (size_t)(colBase + ldRow) * Kelem + kb;
        #pragma unroll
        for (int q = 0; q < 2; q++) {
            int j = ldJ + q;
            uint32_t off = SWZ64(ldRow, j);
            asm volatile("cp.async.cg.shared.global [%0], [%1], 16;" :: "r"(base + off),              "l"(gaH + j * 8));
            asm volatile("cp.async.cg.shared.global [%0], [%1], 16;" :: "r"(base + TILE_B + off),     "l"(gaL + j * 8));
            asm volatile("cp.async.cg.shared.global [%0], [%1], 16;" :: "r"(base + 2 * TILE_B + off), "l"(gbH + j * 8));
            asm volatile("cp.async.cg.shared.global [%0], [%1], 16;" :: "r"(base + 3 * TILE_B + off), "l"(gbL + j * 8));
        }
    };

    issue(0);
    asm volatile("cp.async.commit_group;\n" ::: "memory");
    if (KS > 1) issue(1);
    asm volatile("cp.async.commit_group;\n" ::: "memory");

    // ldmatrix per-lane components
    int aRowC = wm + (lane & 15);
    int aCh   = (lane >> 4) & 1;        // chunk half from k
    int bRowC = wn + (lane & 7) + ((lane & 16) >> 1);
    int bCh   = (lane >> 3) & 1;

    for (int s = 0; s < KS; s++) {
        asm volatile("cp.async.wait_group 1;\n" ::: "memory");
        __syncthreads();

        if (s + 2 < KS) issue(s + 2);
        asm volatile("cp.async.commit_group;\n" ::: "memory");

        uint32_t base = sbase + (s % 3) * 32768;
        #pragma unroll
        for (int kk = 0; kk < 2; kk++) {
            uint32_t aH[2][4], aL[2][4], bH[4][4];
            #pragma unroll
            for (int mi = 0; mi < 2; mi++) {
                int row = aRowC + mi * 16;
                uint32_t off = SWZ64(row, kk * 2 + aCh);
                ldsm4(aH[mi], base + off);
                ldsm4(aL[mi], base + TILE_B + off);
            }
            #pragma unroll
            for (int nt = 0; nt < 4; nt++) {
                int row = bRowC + nt * 16;
                ldsm4(bH[nt], base + 2 * TILE_B + SWZ64(row, kk * 2 + bCh));
            }
            // term 1: Ahi * Bhi
            #pragma unroll
            for (int mi = 0; mi < 2; mi++)
                #pragma unroll
                for (int nt = 0; nt < 4; nt++) {
                    mma16816(acc[mi][nt * 2],     aH[mi], bH[nt][0], bH[nt][1]);
                    mma16816(acc[mi][nt * 2 + 1], aH[mi], bH[nt][2], bH[nt][3]);
                }
            // term 3: Alo * Bhi
            #pragma unroll
            for (int mi = 0; mi < 2; mi++)
                #pragma unroll
                for (int nt = 0; nt < 4; nt++) {
                    mma16816(acc[mi][nt * 2],     aL[mi], bH[nt][0], bH[nt][1]);
                    mma16816(acc[mi][nt * 2 + 1], aL[mi], bH[nt][2], bH[nt][3]);
                }
            // term 2: Ahi * Blo (bL reuses dead bH/aL registers)
            uint32_t bL[4][4];
            #pragma unroll
            for (int nt = 0; nt < 4; nt++) {
                int row = bRowC + nt * 16;
                ldsm4(bL[nt], base + 3 * TILE_B + SWZ64(row, kk * 2 + bCh));
            }
            #pragma unroll
            for (int mi = 0; mi < 2; mi++)
                #pragma unroll
                for (int nt = 0; nt < 4; nt++) {
                    mma16816(acc[mi][nt * 2],     aH[mi], bL[nt][0], bL[nt][1]);
                    mma16816(acc[mi][nt * 2 + 1], aH[mi], bL[nt][2], bL[nt][3]);
                }
        }
    }

    // ---------------- epilogue ----------------
    #pragma unroll
    for (int mi = 0; mi < 2; mi++) {
        #pragma unroll
        for (int half = 0; half < 2; half++) {
            int r = rowBase + wm + mi * 16 + (lane >> 2) + half * 8;
            int tE = (mode == 3) ? d_TT[r] : 0;
            #pragma unroll
            for (int ni = 0; ni < 8; ni++) {
                int c = colBase + wn + ni * 8 + (lane & 3) * 2;
                float v0 = acc[mi][ni][half * 2 + 0] + bias[c];
                float v1 = acc[mi][ni][half * 2 + 1] + bias[c + 1];
                if (mode == 0) {
                    float2 v; v.x = v0; v.y = v1;
                    *reinterpret_cast<float2*>(&outF[(size_t)r * ldOut + c]) = v;
                } else {
                    if (mode == 1) {
                        v0 = fmaxf(v0, 0.f); v1 = fmaxf(v1, 0.f);
                    } else if (mode == 2) {
                        v0 = v0 / (1.f + expf(-v0)); v1 = v1 / (1.f + expf(-v1));
                    } else {
                        v0 += emb[(size_t)tE * DIMT + c];
                        v1 += emb[(size_t)tE * DIMT + c + 1];
                    }
                    __nv_bfloat16 h0 = __float2bfloat16(v0), h1 = __float2bfloat16(v1);
                    __nv_bfloat162 hh, ll;
                    hh.x = h0; hh.y = h1;
                    ll.x = __float2bfloat16(v0 - __bfloat162float(h0));
                    ll.y = __float2bfloat16(v1 - __bfloat162float(h1));
                    *reinterpret_cast<__nv_bfloat162*>(&outH[(size_t)r * ldOut + c]) = hh;
                    *reinterpret_cast<__nv_bfloat162*>(&outL[(size_t)r * ldOut + c]) = ll;
                }
            }
        }
    }
}

// ---------------- per-row loss (OUT stride = NPAD2) -----------------------
__global__ __launch_bounds__(256) void loss_kernel(const float* __restrict__ noise) {
    int warp = threadIdx.x >> 5, lane = threadIdx.x & 31;
    int b = blockIdx.x * 8 + warp;
    __shared__ float s_row[8];
    int t = d_TT[b];
    int tm1 = (t > 0) ? t - 1 : 0;
    const float* outp = d_OUT + (size_t)b * NPAD2;

    float g = 0.f;
    if (lane < NNUM) { float d = noise[b * NNUM + lane] - outp[lane]; g = d * d; }

    float kl = 0.f, dec = 0.f;
    if (lane < NCAT) {
        int hot = d_CAT[b * NCAT + lane];
        int sm  = d_SAMP[b * NCAT + lane];
        const float* oc = outp + NNUM + lane * KCLS;
        float v[KCLS];
        float mx = -1e30f;
        #pragma unroll
        for (int k = 0; k < KCLS; k++) { v[k] = oc[k]; mx = fmaxf(mx, v[k]); }
        float se = 0.f;
        #pragma unroll
        for (int k = 0; k < KCLS; k++) se += expf(v[k] - mx);
        float lse = mx + logf(se);

        float PH = laddexp(d_LOG_A[t], d_LOG_1M_A[t] - LOGK_F);
        float PO = laddexp(CL_F + d_LOG_A[t], d_LOG_1M_A[t] - LOGK_F);
        float H1, O1;
        if (t == 0) { H1 = 0.f; O1 = CL_F; }
        else {
            H1 = laddexp(d_LOG_CA[tm1], d_LOG_1M_CA[tm1] - LOGK_F);
            O1 = laddexp(CL_F + d_LOG_CA[tm1], d_LOG_1M_CA[tm1] - LOGK_F);
        }

        float unm[KCLS], unt[KCLS];
        float mmax = -1e30f, tmax = -1e30f;
        #pragma unroll
        for (int k = 0; k < KCLS; k++) {
            float lx0 = v[k] - lse;
            float ev  = (t == 0) ? lx0
                                 : laddexp(lx0 + d_LOG_CA[tm1], d_LOG_1M_CA[tm1] - LOGK_F);
            float pk  = (k == sm) ? PH : PO;
            float um = ev + pk;            unm[k] = um; mmax = fmaxf(mmax, um);
            float ut = ((k == hot) ? H1 : O1) + pk; unt[k] = ut; tmax = fmaxf(tmax, ut);
        }
        float ms = 0.f, ts = 0.f;
        #pragma unroll
        for (int k = 0; k < KCLS; k++) { ms += expf(unm[k] - mmax); ts += expf(unt[k] - tmax); }
        float mlse = mmax + logf(ms), tlse = tmax + logf(ts);
        float EXPL = expf(CL_F);
        #pragma unroll
        for (int k = 0; k < KCLS; k++) {
            float lt = unt[k] - tlse, lm = unm[k] - mlse;
            kl  += expf(lt) * (lt - lm);
            dec -= ((k == hot) ? 1.0f : EXPL) * lm;
        }
    }

    #pragma unroll
    for (int o = 16; o; o >>= 1) {
        g   += __shfl_xor_sync(0xffffffffu, g, o);
        kl  += __shfl_xor_sync(0xffffffffu, kl, o);
        dec += __shfl_xor_sync(0xffffffffu, dec, o);
    }
    if (lane == 0) {
        float Lt = (t == 0) ? dec : kl;
        s_row[warp] = (Lt + d_KLP) * (1.0f / ((float)NCAT * (float)BATCH))
                    + g * (1.0f / ((float)NNUM * (float)BATCH));
    }
    __syncthreads();
    if (threadIdx.x == 0) {
        float s = 0.f;
        #pragma unroll
        for (int i = 0; i < 8; i++) s += s_row[i];
        d_PART[blockIdx.x] = s;
    }
}

__global__ void final_kernel(float* __restrict__ out) {
    __shared__ float s[256];
    float a = 0.f;
    for (int i = threadIdx.x; i < BATCH / 8; i += 256) a += d_PART[i];
    s[threadIdx.x] = a;
    __syncthreads();
    for (int st = 128; st; st >>= 1) {
        if (threadIdx.x < st) s[threadIdx.x] += s[threadIdx.x + st];
        __syncthreads();
    }
    if (threadIdx.x == 0) out[0] = s[0];
}

// ---------------- launch ----------------
extern "C" void kernel_launch(void* const* d_in, const int* in_sizes, int n_in,
                              void* d_out, int out_size) {
    const float* x_num   = (const float*)d_in[0];
    const int*   x_cat_r = (const int*)  d_in[1];
    const int*   t_r     = (const int*)  d_in[2];
    const float* noise   = (const float*)d_in[3];
    const float* gumbel  = (const float*)d_in[4];
    const float* te_w1   = (const float*)d_in[5];
    const float* te_b1   = (const float*)d_in[6];
    const float* te_w2   = (const float*)d_in[7];
    const float* te_b2   = (const float*)d_in[8];
    const float* proj_w  = (const float*)d_in[9];
    const float* proj_b  = (const float*)d_in[10];
    const float* mlp_w1  = (const float*)d_in[11];
    const float* mlp_b1  = (const float*)d_in[12];
    const float* mlp_w2  = (const float*)d_in[13];
    const float* mlp_b2  = (const float*)d_in[14];
    float* out = (float*)d_out;

    cudaFuncSetAttribute(mma_gemm, cudaFuncAttributeMaxDynamicSharedMemorySize, GSMEM_BYTES);

    __nv_bfloat16 *pE0H, *pE0L, *pE1H, *pE1L;
    __nv_bfloat16 *pW1H, *pW1L, *pW2H, *pW2L, *pM1H, *pM1L, *pM2H, *pM2L, *pPJH, *pPJL;
    __nv_bfloat16 *pXIH, *pXIL, *pHH, *pHL, *pUH, *pUL;
    float *pEMB, *pOUT, *pB2;
    cudaGetSymbolAddress((void**)&pE0H, d_E0H); cudaGetSymbolAddress((void**)&pE0L, d_E0L);
    cudaGetSymbolAddress((void**)&pE1H, d_E1H); cudaGetSymbolAddress((void**)&pE1L, d_E1L);
    cudaGetSymbolAddress((void**)&pW1H, d_W1TH); cudaGetSymbolAddress((void**)&pW1L, d_W1TL);
    cudaGetSymbolAddress((void**)&pW2H, d_W2TH); cudaGetSymbolAddress((void**)&pW2L, d_W2TL);
    cudaGetSymbolAddress((void**)&pM1H, d_M1TH); cudaGetSymbolAddress((void**)&pM1L, d_M1TL);
    cudaGetSymbolAddress((void**)&pM2H, d_M2TH); cudaGetSymbolAddress((void**)&pM2L, d_M2TL);
    cudaGetSymbolAddress((void**)&pPJH, d_PJTH); cudaGetSymbolAddress((void**)&pPJL, d_PJTL);
    cudaGetSymbolAddress((void**)&pXIH, d_XINH); cudaGetSymbolAddress((void**)&pXIL, d_XINL);
    cudaGetSymbolAddress((void**)&pHH, d_HH); cudaGetSymbolAddress((void**)&pHL, d_HL);
    cudaGetSymbolAddress((void**)&pUH, d_UH); cudaGetSymbolAddress((void**)&pUL, d_UL);
    cudaGetSymbolAddress((void**)&pEMB, d_EMB); cudaGetSymbolAddress((void**)&pOUT, d_OUT);
    cudaGetSymbolAddress((void**)&pB2, d_B2P);

    sched_kernel<<<1, 1024>>>();                                      // our 1
    detect_kernel<<<1, 32>>>(t_r, x_cat_r);                           // our 2
    prep_kernel<<<9728, dim3(32, 8)>>>(t_r, x_cat_r, mlp_b2,
                                       te_w1, te_w2, mlp_w1, mlp_w2, proj_w); // our 3

    // te MLP over 1024 (padded) unique timesteps  — our 4: ncu-profiled launch
    mma_gemm<<<dim3(DIMT / 128, TPAD / 128), 256, GSMEM_BYTES>>>(
        pE0H, pE0L, pW1H, pW1L, te_b1, nullptr, pE1H, pE1L, nullptr, DIMT, DIMT, /*silu*/2);
    mma_gemm<<<dim3(DIMT / 128, TPAD / 128), 256, GSMEM_BYTES>>>(
        pE1H, pE1L, pW2H, pW2L, te_b2, pEMB, nullptr, nullptr, nullptr, DIMT, DIMT, /*fp32*/0);

    build_xin_kernel<<<BATCH, 128>>>(x_num, noise, gumbel);

    // proj: h = x_in@proj_w + proj_b + emb[t]   -> hi/lo
    mma_gemm<<<dim3(DIMT / 128, BATCH / 128), 256, GSMEM_BYTES>>>(
        pXIH, pXIL, pPJH, pPJL, proj_b, nullptr, pHH, pHL, pEMB, KPAD, DIMT, /*emb*/3);
    // mlp1: relu -> hi/lo
    mma_gemm<<<dim3(HIDN / 128, BATCH / 128), 256, GSMEM_BYTES>>>(
        pHH, pHL, pM1H, pM1L, mlp_b1, nullptr, pUH, pUL, nullptr, DIMT, HIDN, /*relu*/1);
    // mlp2: fp32 out (padded to 512)
    mma_gemm<<<dim3(NPAD2 / 128, BATCH / 128), 256, GSMEM_BYTES>>>(
        pUH, pUL, pM2H, pM2L, pB2, pOUT, nullptr, nullptr, nullptr, HIDN, NPAD2, /*fp32*/0);

    loss_kernel<<<BATCH / 8, 256>>>(noise);
    final_kernel<<<1, 256>>>(out);
}

// round 17
// speedup vs baseline: 1.7658x; 1.0853x over previous
#include <cuda_runtime.h>
#include <cuda_bf16.h>
#include <math.h>
#include <stdint.h>

// ---------------- problem constants ----------------
#define BATCH  16384
#define NNUM   16
#define NCAT   24
#define KCLS   16
#define CATDIM 384
#define DIN    400
#define KPAD   416          // padded DIN for proj GEMM (13 x 32)
#define DIMT   1024
#define HIDN   1024
#define NPAD2  512          // padded DIN for mlp2 output
#define TSTEPS 1000
#define TPAD   1024

#define LOGK_F 2.772588722239781f
#define CL_F   (-69.07755278982137f)

// ---------------- device scratch ----------------
__device__ float d_LOG_A[TSTEPS], d_LOG_1M_A[TSTEPS];
__device__ float d_LOG_CA[TSTEPS], d_LOG_1M_CA[TSTEPS];
__device__ float d_SQAC[TSTEPS], d_SQ1MAC[TSTEPS];
__device__ float d_KLP;
__device__ int   d_t64, d_c64;
__device__ int   d_TT[BATCH];
__device__ int   d_CAT[BATCH * NCAT];
__device__ int   d_SAMP[BATCH * NCAT];

__device__ __nv_bfloat16 d_E0H[TPAD * DIMT], d_E0L[TPAD * DIMT];
__device__ __nv_bfloat16 d_E1H[TPAD * DIMT], d_E1L[TPAD * DIMT];
__device__ float         d_EMB[TPAD * DIMT];
__device__ __nv_bfloat16 d_W1TH[DIMT * DIMT], d_W1TL[DIMT * DIMT];   // te_w1^T
__device__ __nv_bfloat16 d_W2TH[DIMT * DIMT], d_W2TL[DIMT * DIMT];   // te_w2^T
__device__ __nv_bfloat16 d_M1TH[HIDN * DIMT], d_M1TL[HIDN * DIMT];   // mlp_w1^T
__device__ __nv_bfloat16 d_M2TH[NPAD2 * HIDN], d_M2TL[NPAD2 * HIDN]; // mlp_w2^T padded
__device__ __nv_bfloat16 d_PJTH[DIMT * KPAD], d_PJTL[DIMT * KPAD];   // proj_w^T padded
__device__ __nv_bfloat16 d_XINH[(size_t)BATCH * KPAD], d_XINL[(size_t)BATCH * KPAD];
__device__ __nv_bfloat16 d_HH[(size_t)BATCH * DIMT], d_HL[(size_t)BATCH * DIMT];
__device__ __nv_bfloat16 d_UH[(size_t)BATCH * DIMT], d_UL[(size_t)BATCH * DIMT];
__device__ float         d_OUT[(size_t)BATCH * NPAD2];
__device__ float         d_B2P[NPAD2];
__device__ float d_PART[BATCH / 8];

// ---------------- helpers ----------------
__device__ __forceinline__ float laddexp(float a, float b) {
    float m = fmaxf(a, b);
    return m + logf(expf(a - m) + expf(b - m));
}
__device__ __forceinline__ uint32_t smem_u32(const void* p) {
    return (uint32_t)__cvta_generic_to_shared(p);
}
// 64B-row tile swizzle: conflict-free for 8-row ldmatrix groups
#define SWZ64(row, chunk) ((uint32_t)((row) * 64 + ((((chunk) ^ (((row) >> 1) & 3))) << 4)))

__device__ __forceinline__ void ldsm4(uint32_t* r, uint32_t addr) {
    asm volatile("ldmatrix.sync.aligned.m8n8.x4.shared.b16 {%0,%1,%2,%3}, [%4];"
        : "=r"(r[0]), "=r"(r[1]), "=r"(r[2]), "=r"(r[3]) : "r"(addr));
}
__device__ __forceinline__ void mma16816(float* c, const uint32_t* a, uint32_t b0, uint32_t b1) {
    asm volatile("mma.sync.aligned.m16n8k16.row.col.f32.bf16.bf16.f32 "
        "{%0,%1,%2,%3}, {%4,%5,%6,%7}, {%8,%9}, {%0,%1,%2,%3};"
        : "+f"(c[0]), "+f"(c[1]), "+f"(c[2]), "+f"(c[3])
        : "r"(a[0]), "r"(a[1]), "r"(a[2]), "r"(a[3]), "r"(b0), "r"(b1));
}

// ---------------- schedules ----------------
__global__ void sched_kernel() {
    __shared__ double s[1024];
    int i = threadIdx.x;
    const double PI = 3.14159265358979323846;
    double la = 0.0;
    if (i < TSTEPS) {
        double u0 = (double)i / (double)TSTEPS;
        double u1 = (double)(i + 1) / (double)TSTEPS;
        double c0 = cos((u0 + 0.008) / 1.008 * PI / 2.0); double ab0 = c0 * c0;
        double c1 = cos((u1 + 0.008) / 1.008 * PI / 2.0); double ab1 = c1 * c1;
        double beta = 1.0 - ab1 / ab0;
        if (beta > 0.999) beta = 0.999;
        la = log(1.0 - beta);
    }
    s[i] = la;
    __syncthreads();
    #pragma unroll
    for (int off = 1; off < 1024; off <<= 1) {
        double v = (i >= off) ? s[i - off] : 0.0;
        __syncthreads();
        s[i] += v;
        __syncthreads();
    }
    if (i < TSTEPS) {
        double lca = s[i];
        d_LOG_A[i]     = (float)la;
        d_LOG_1M_A[i]  = (float)log(1.0 - exp(la) + 1e-40);
        d_LOG_CA[i]    = (float)lca;
        d_LOG_1M_CA[i] = (float)log(1.0 - exp(lca) + 1e-40);
        double ac = exp(lca);
        d_SQAC[i]   = (float)sqrt(ac);
        d_SQ1MAC[i] = (float)sqrt(1.0 - ac);
    }
    __syncthreads();
    if (i == 0) {
        float lcaT = d_LOG_CA[TSTEPS - 1], l1mT = d_LOG_1M_CA[TSTEPS - 1];
        float hT = laddexp(lcaT, l1mT - LOGK_F);
        float oT = laddexp(CL_F + lcaT, l1mT - LOGK_F);
        d_KLP = (float)NCAT * (expf(hT) * (hT + LOGK_F) + 15.0f * expf(oT) * (oT + LOGK_F));
    }
}

// ---------------- dtype sniff ----------------
__global__ void detect_kernel(const int* __restrict__ traw, const int* __restrict__ craw) {
    if (threadIdx.x != 0) return;
    int z = 1;
    for (int i = 0; i < 64; i++) if (traw[2 * i + 1] != 0) { z = 0; break; }
    d_t64 = z;
    z = 1;
    for (int i = 0; i < 64; i++) if (craw[2 * i + 1] != 0) { z = 0; break; }
    d_c64 = z;
}

// ---------------- transpose helper ----------------
__device__ __forceinline__ void do_transpose(
    const float* __restrict__ in, int R, int C, int Rpad,
    __nv_bfloat16* __restrict__ oh, __nv_bfloat16* __restrict__ ol,
    int bx, int by)
{
    __shared__ float tl[32][33];
    int c0 = bx * 32, r0 = by * 32;
    #pragma unroll
    for (int k = 0; k < 4; k++) {
        int r = r0 + threadIdx.y + k * 8;
        int c = c0 + threadIdx.x;
        float v = (r < R && c < C) ? in[(size_t)r * C + c] : 0.f;
        tl[threadIdx.x][threadIdx.y + k * 8] = v;
    }
    __syncthreads();
    #pragma unroll
    for (int k = 0; k < 4; k++) {
        int c = c0 + threadIdx.y + k * 8;   // out row
        int r = r0 + threadIdx.x;           // out col
        float v = tl[threadIdx.y + k * 8][threadIdx.x];
        __nv_bfloat16 h = __float2bfloat16(v);
        oh[(size_t)c * Rpad + r] = h;
        ol[(size_t)c * Rpad + r] = __float2bfloat16(v - __bfloat162float(h));
    }
}

// ---------------- ONE prep kernel: converts + temb + all transposes -------
// blocks: [0,1536) convert | [1536,5632) temb | [5632,9632) transposes
__global__ void prep_kernel(
    const int* __restrict__ traw, const int* __restrict__ craw,
    const float* __restrict__ b2,
    const float* __restrict__ te_w1, const float* __restrict__ te_w2,
    const float* __restrict__ mlp_w1, const float* __restrict__ mlp_w2,
    const float* __restrict__ proj_w)
{
    int b = blockIdx.x;
    int tid = threadIdx.y * 32 + threadIdx.x;
    if (b < 1536) {
        int i = b * 256 + tid;
        if (i < BATCH) d_TT[i] = d_t64 ? traw[2 * i] : traw[i];
        if (i < BATCH * NCAT) d_CAT[i] = d_c64 ? craw[2 * i] : craw[i];
        if (i < NPAD2) d_B2P[i] = (i < DIN) ? b2[i] : 0.f;
    } else if (b < 5632) {
        int idx = b - 1536;
        int t = idx >> 2;
        int j = (idx & 3) * 256 + tid;
        float v = 0.f;
        if (t < TSTEPS) {
            int h = j & 511;
            float freq = expf(-9.210340371976184f * (float)h / 512.0f);
            float arg = (float)t * freq;
            v = (j < 512) ? cosf(arg) : sinf(arg);
        }
        __nv_bfloat16 hi = __float2bfloat16(v);
        __nv_bfloat16 lo = __float2bfloat16(v - __bfloat162float(hi));
        d_E0H[t * DIMT + j] = hi;
        d_E0L[t * DIMT + j] = lo;
    } else {
        b -= 5632;
        if (b < 1024) {
            do_transpose(te_w1, DIMT, DIMT, DIMT, d_W1TH, d_W1TL, b & 31, b >> 5);
        } else if (b < 2048) {
            b -= 1024;
            do_transpose(te_w2, DIMT, DIMT, DIMT, d_W2TH, d_W2TL, b & 31, b >> 5);
        } else if (b < 3072) {
            b -= 2048;
            do_transpose(mlp_w1, DIMT, HIDN, DIMT, d_M1TH, d_M1TL, b & 31, b >> 5);
        } else if (b < 3584) {
            b -= 3072;                               // 16 x 32 blocks
            do_transpose(mlp_w2, HIDN, DIN, HIDN, d_M2TH, d_M2TL, b & 15, b >> 4);
        } else {
            b -= 3584;                               // 32 x 13 blocks
            do_transpose(proj_w, DIN, DIMT, KPAD, d_PJTH, d_PJTL, b & 31, b >> 5);
        }
    }
}

// ---------------- build x_in (hi/lo bf16, padded to 416) + sampling -------
__global__ __launch_bounds__(128) void build_xin_kernel(
    const float* __restrict__ x_num, const float* __restrict__ noise,
    const float* __restrict__ gumbel) {
    int b = blockIdx.x;
    int tid = threadIdx.x;
    __shared__ float s_x[NNUM];
    __shared__ int   s_s[NCAT];
    int t = d_TT[b];

    if (tid < NNUM)
        s_x[tid] = d_SQAC[t] * x_num[b * NNUM + tid] + d_SQ1MAC[t] * noise[b * NNUM + tid];
    if (tid < NCAT) {
        int hot = d_CAT[b * NCAT + tid];
        float hv = laddexp(d_LOG_CA[t], d_LOG_1M_CA[t] - LOGK_F);
        float ov = laddexp(CL_F + d_LOG_CA[t], d_LOG_1M_CA[t] - LOGK_F);
        const float* gp = gumbel + (size_t)b * CATDIM + tid * KCLS;
        float best = -1e30f; int bi = 0;
        #pragma unroll
        for (int k = 0; k < KCLS; k++) {
            float g = -logf(-logf(gp[k] + 1e-30f) + 1e-30f);
            float v = g + ((k == hot) ? hv : ov);
            if (v > best) { best = v; bi = k; }
        }
        s_s[tid] = bi;
        d_SAMP[b * NCAT + tid] = bi;
    }
    __syncthreads();

    const __nv_bfloat16 clh = __float2bfloat16(CL_F);
    const __nv_bfloat16 cll = __float2bfloat16(CL_F - __bfloat162float(clh));
    for (int j = tid; j < KPAD; j += 128) {
        __nv_bfloat16 h, l;
        if (j < NNUM) {
            float v = s_x[j];
            h = __float2bfloat16(v);
            l = __float2bfloat16(v - __bfloat162float(h));
        } else if (j < DIN) {
            int c = (j - NNUM) >> 4, k = (j - NNUM) & 15;
            if (k == s_s[c]) { h = __float2bfloat16(0.f); l = h; }
            else { h = clh; l = cll; }
        } else {
            h = __float2bfloat16(0.f); l = h;
        }
        d_XINH[(size_t)b * KPAD + j] = h;
        d_XINL[(size_t)b * KPAD + j] = l;
    }
}

// ---------------- fused 3-term bf16 mma.sync GEMM (M-tile 128) -----------
// BK=32 (64B rows), 3-stage cp.async, 96KB smem -> 2 CTAs/SM.
// mode 0: fp32 out   1: relu->hi/lo   2: silu->hi/lo   3: +emb[t[row]]->hi/lo
#define GSMEM_BYTES 98304
#define TILE_B 8192
__global__ __launch_bounds__(256, 2) void mma_gemm(
    const __nv_bfloat16* __restrict__ Ahi, const __nv_bfloat16* __restrict__ Alo,
    const __nv_bfloat16* __restrict__ Bhi, const __nv_bfloat16* __restrict__ Blo,
    const float* __restrict__ bias,
    float* __restrict__ outF, __nv_bfloat16* __restrict__ outH, __nv_bfloat16* __restrict__ outL,
    const float* __restrict__ emb,
    int Kelem, int ldOut, int mode)
{
    extern __shared__ char smem[];
    const uint32_t sbase = smem_u32(smem);      // 3 stages x 32KB: Ahi|Alo|Bhi|Blo (8KB each)
    int tid = threadIdx.x, wid = tid >> 5, lane = tid & 31;
    int wm = (wid & 3) * 32, wn = (wid >> 2) * 64;
    int rowBase = blockIdx.y * 128, colBase = blockIdx.x * 128;

    int KS = Kelem >> 5;                         // 32-wide k-blocks

    int c0 = tid * 2;
    int ldRow = c0 >> 2;          // 0..127
    int ldJ   = c0 & 3;           // starting chunk (0 or 2)

    float acc[2][8][4];
    #pragma unroll
    for (int a = 0; a < 2; a++)
        #pragma unroll
        for (int b = 0; b < 8; b++)
            #pragma unroll
            for (int c = 0; c < 4; c++) acc[a][b][c] = 0.f;

    auto issue = [&](int s) {
        int kb = s << 5;
        uint32_t base = sbase + (s % 3) * 32768;
        const __nv_bfloat16* gaH = Ahi + (size_t)(rowBase + ldRow) * Kelem + kb;
        const __nv_bfloat16* gaL = Alo + (size_t)(rowBase + ldRow) * Kelem + kb;
        const __nv_bfloat16* gbH = Bhi + (size_t)(colBase + ldRow) * Kelem + kb;
        const __nv_bfloat16* gbL = Blo + (size_t)(colBase + ldRow) * Kelem + kb;
        #pragma unroll
        for (int q = 0; q < 2; q++) {
            int j = ldJ + q;
            uint32_t off = SWZ64(ldRow, j);
            asm volatile("cp.async.cg.shared.global [%0], [%1], 16;" :: "r"(base + off),              "l"(gaH + j * 8));
            asm volatile("cp.async.cg.shared.global [%0], [%1], 16;" :: "r"(base + TILE_B + off),     "l"(gaL + j * 8));
            asm volatile("cp.async.cg.shared.global [%0], [%1], 16;" :: "r"(base + 2 * TILE_B + off), "l"(gbH + j * 8));
            asm volatile("cp.async.cg.shared.global [%0], [%1], 16;" :: "r"(base + 3 * TILE_B + off), "l"(gbL + j * 8));
        }
    };

    issue(0);
    asm volatile("cp.async.commit_group;\n" ::: "memory");
    if (KS > 1) issue(1);
    asm volatile("cp.async.commit_group;\n" ::: "memory");

    int aRowC = wm + (lane & 15);
    int aCh   = (lane >> 4) & 1;
    int bRowC = wn + (lane & 7) + ((lane & 16) >> 1);
    int bCh   = (lane >> 3) & 1;

    for (int s = 0; s < KS; s++) {
        asm volatile("cp.async.wait_group 1;\n" ::: "memory");
        __syncthreads();

        if (s + 2 < KS) issue(s + 2);
        asm volatile("cp.async.commit_group;\n" ::: "memory");

        uint32_t base = sbase + (s % 3) * 32768;
        #pragma unroll
        for (int kk = 0; kk < 2; kk++) {
            uint32_t aH[2][4], aL[2][4], bH[4][4];
            #pragma unroll
            for (int mi = 0; mi < 2; mi++) {
                int row = aRowC + mi * 16;
                uint32_t off = SWZ64(row, kk * 2 + aCh);
                ldsm4(aH[mi], base + off);
                ldsm4(aL[mi], base + TILE_B + off);
            }
            #pragma unroll
            for (int nt = 0; nt < 4; nt++) {
                int row = bRowC + nt * 16;
                ldsm4(bH[nt], base + 2 * TILE_B + SWZ64(row, kk * 2 + bCh));
            }
            #pragma unroll
            for (int mi = 0; mi < 2; mi++)
                #pragma unroll
                for (int nt = 0; nt < 4; nt++) {
                    mma16816(acc[mi][nt * 2],     aH[mi], bH[nt][0], bH[nt][1]);
                    mma16816(acc[mi][nt * 2 + 1], aH[mi], bH[nt][2], bH[nt][3]);
                }
            #pragma unroll
            for (int mi = 0; mi < 2; mi++)
                #pragma unroll
                for (int nt = 0; nt < 4; nt++) {
                    mma16816(acc[mi][nt * 2],     aL[mi], bH[nt][0], bH[nt][1]);
                    mma16816(acc[mi][nt * 2 + 1], aL[mi], bH[nt][2], bH[nt][3]);
                }
            uint32_t bL[4][4];
            #pragma unroll
            for (int nt = 0; nt < 4; nt++) {
                int row = bRowC + nt * 16;
                ldsm4(bL[nt], base + 3 * TILE_B + SWZ64(row, kk * 2 + bCh));
            }
            #pragma unroll
            for (int mi = 0; mi < 2; mi++)
                #pragma unroll
                for (int nt = 0; nt < 4; nt++) {
                    mma16816(acc[mi][nt * 2],     aH[mi], bL[nt][0], bL[nt][1]);
                    mma16816(acc[mi][nt * 2 + 1], aH[mi], bL[nt][2], bL[nt][3]);
                }
        }
    }

    #pragma unroll
    for (int mi = 0; mi < 2; mi++) {
        #pragma unroll
        for (int half = 0; half < 2; half++) {
            int r = rowBase + wm + mi * 16 + (lane >> 2) + half * 8;
            int tE = (mode == 3) ? d_TT[r] : 0;
            #pragma unroll
            for (int ni = 0; ni < 8; ni++) {
                int c = colBase + wn + ni * 8 + (lane & 3) * 2;
                float v0 = acc[mi][ni][half * 2 + 0] + bias[c];
                float v1 = acc[mi][ni][half * 2 + 1] + bias[c + 1];
                if (mode == 0) {
                    float2 v; v.x = v0; v.y = v1;
                    *reinterpret_cast<float2*>(&outF[(size_t)r * ldOut + c]) = v;
                } else {
                    if (mode == 1) {
                        v0 = fmaxf(v0, 0.f); v1 = fmaxf(v1, 0.f);
                    } else if (mode == 2) {
                        v0 = v0 / (1.f + expf(-v0)); v1 = v1 / (1.f + expf(-v1));
                    } else {
                        v0 += emb[(size_t)tE * DIMT + c];
                        v1 += emb[(size_t)tE * DIMT + c + 1];
                    }
                    __nv_bfloat16 h0 = __float2bfloat16(v0), h1 = __float2bfloat16(v1);
                    __nv_bfloat162 hh, ll;
                    hh.x = h0; hh.y = h1;
                    ll.x = __float2bfloat16(v0 - __bfloat162float(h0));
                    ll.y = __float2bfloat16(v1 - __bfloat162float(h1));
                    *reinterpret_cast<__nv_bfloat162*>(&outH[(size_t)r * ldOut + c]) = hh;
                    *reinterpret_cast<__nv_bfloat162*>(&outL[(size_t)r * ldOut + c]) = ll;
                }
            }
        }
    }
}

// ---------------- M-tile-64 variant for the small te GEMMs ---------------
// 8 warps as 2M x 4N (warp 32x32); stage = 4+4+8+8 = 24KB; grid fills chip.
#define GSMEM64 73728
#define TA64 4096
__global__ __launch_bounds__(256, 2) void mma_gemm64(
    const __nv_bfloat16* __restrict__ Ahi, const __nv_bfloat16* __restrict__ Alo,
    const __nv_bfloat16* __restrict__ Bhi, const __nv_bfloat16* __restrict__ Blo,
    const float* __restrict__ bias,
    float* __restrict__ outF, __nv_bfloat16* __restrict__ outH, __nv_bfloat16* __restrict__ outL,
    int Kelem, int ldOut, int mode)   // mode 0: fp32  2: silu->hi/lo
{
    extern __shared__ char smem[];
    const uint32_t sbase = smem_u32(smem);   // per stage: Ahi 4K | Alo 4K | Bhi 8K | Blo 8K
    int tid = threadIdx.x, wid = tid >> 5, lane = tid & 31;
    int wm = (wid & 1) * 32, wn = (wid >> 1) * 32;
    int rowBase = blockIdx.y * 64, colBase = blockIdx.x * 128;

    int KS = Kelem >> 5;

    // A: 1 chunk per thread (256 chunks); B: 2 chunks per thread (512 chunks)
    int raA = tid >> 2, jaA = tid & 3;
    int c0 = tid * 2;
    int rbB = c0 >> 2, jbB = c0 & 3;

    float acc[2][4][4];
    #pragma unroll
    for (int a = 0; a < 2; a++)
        #pragma unroll
        for (int b = 0; b < 4; b++)
            #pragma unroll
            for (int c = 0; c < 4; c++) acc[a][b][c] = 0.f;

    auto issue = [&](int s) {
        int kb = s << 5;
        uint32_t base = sbase + (s % 3) * 24576;
        const __nv_bfloat16* gaH = Ahi + (size_t)(rowBase + raA) * Kelem + kb;
        const __nv_bfloat16* gaL = Alo + (size_t)(rowBase + raA) * Kelem + kb;
        uint32_t offA = SWZ64(raA, jaA);
        asm volatile("cp.async.cg.shared.global [%0], [%1], 16;" :: "r"(base + offA),        "l"(gaH + jaA * 8));
        asm volatile("cp.async.cg.shared.global [%0], [%1], 16;" :: "r"(base + TA64 + offA), "l"(gaL + jaA * 8));
        const __nv_bfloat16* gbH = Bhi + (size_t)(colBase + rbB) * Kelem + kb;
        const __nv_bfloat16* gbL = Blo + (size_t)(colBase + rbB) * Kelem + kb;
        #pragma unroll
        for (int q = 0; q < 2; q++) {
            int j = jbB + q;
            uint32_t off = SWZ64(rbB, j);
            asm volatile("cp.async.cg.shared.global [%0], [%1], 16;" :: "r"(base + 2 * TA64 + off),          "l"(gbH + j * 8));
            asm volatile("cp.async.cg.shared.global [%0], [%1], 16;" :: "r"(base + 2 * TA64 + TILE_B + off), "l"(gbL + j * 8));
        }
    };

    issue(0);
    asm volatile("cp.async.commit_group;\n" ::: "memory");
    if (KS > 1) issue(1);
    asm volatile("cp.async.commit_group;\n" ::: "memory");

    int aRowC = wm + (lane & 15);
    int aCh   = (lane >> 4) & 1;
    int bRowC = wn + (lane & 7) + ((lane & 16) >> 1);
    int bCh   = (lane >> 3) & 1;

    for (int s = 0; s < KS; s++) {
        asm volatile("cp.async.wait_group 1;\n" ::: "memory");
        __syncthreads();

        if (s + 2 < KS) issue(s + 2);
        asm volatile("cp.async.commit_group;\n" ::: "memory");

        uint32_t base = sbase + (s % 3) * 24576;
        #pragma unroll
        for (int kk = 0; kk < 2; kk++) {
            uint32_t aH[2][4], aL[2][4], bH[2][4], bL[2][4];
            #pragma unroll
            for (int mi = 0; mi < 2; mi++) {
                int row = aRowC + mi * 16;
                uint32_t off = SWZ64(row, kk * 2 + aCh);
                ldsm4(aH[mi], base + off);
                ldsm4(aL[mi], base + TA64 + off);
            }
            #pragma unroll
            for (int nt = 0; nt < 2; nt++) {
                int row = bRowC + nt * 16;
                uint32_t off = SWZ64(row, kk * 2 + bCh);
                ldsm4(bH[nt], base + 2 * TA64 + off);
                ldsm4(bL[nt], base + 2 * TA64 + TILE_B + off);
            }
            #pragma unroll
            for (int mi = 0; mi < 2; mi++)
                #pragma unroll
                for (int nt = 0; nt < 2; nt++) {
                    mma16816(acc[mi][nt * 2],     aH[mi], bH[nt][0], bH[nt][1]);
                    mma16816(acc[mi][nt * 2 + 1], aH[mi], bH[nt][2], bH[nt][3]);
                    mma16816(acc[mi][nt * 2],     aL[mi], bH[nt][0], bH[nt][1]);
                    mma16816(acc[mi][nt * 2 + 1], aL[mi], bH[nt][2], bH[nt][3]);
                    mma16816(acc[mi][nt * 2],     aH[mi], bL[nt][0], bL[nt][1]);
                    mma16816(acc[mi][nt * 2 + 1], aH[mi], bL[nt][2], bL[nt][3]);
                }
        }
    }

    #pragma unroll
    for (int mi = 0; mi < 2; mi++) {
        #pragma unroll
        for (int half = 0; half < 2; half++) {
            int r = rowBase + wm + mi * 16 + (lane >> 2) + half * 8;
            #pragma unroll
            for (int ni = 0; ni < 4; ni++) {
                int c = colBase + wn + ni * 8 + (lane & 3) * 2;
                float v0 = acc[mi][ni][half * 2 + 0] + bias[c];
                float v1 = acc[mi][ni][half * 2 + 1] + bias[c + 1];
                if (mode == 0) {
                    float2 v; v.x = v0; v.y = v1;
                    *reinterpret_cast<float2*>(&outF[(size_t)r * ldOut + c]) = v;
                } else {
                    v0 = v0 / (1.f + expf(-v0)); v1 = v1 / (1.f + expf(-v1));
                    __nv_bfloat16 h0 = __float2bfloat16(v0), h1 = __float2bfloat16(v1);
                    __nv_bfloat162 hh, ll;
                    hh.x = h0; hh.y = h1;
                    ll.x = __float2bfloat16(v0 - __bfloat162float(h0));
                    ll.y = __float2bfloat16(v1 - __bfloat162float(h1));
                    *reinterpret_cast<__nv_bfloat162*>(&outH[(size_t)r * ldOut + c]) = hh;
                    *reinterpret_cast<__nv_bfloat162*>(&outL[(size_t)r * ldOut + c]) = ll;
                }
            }
        }
    }
}

// ---------------- per-row loss (OUT stride = NPAD2) -----------------------
__global__ __launch_bounds__(256) void loss_kernel(const float* __restrict__ noise) {
    int warp = threadIdx.x >> 5, lane = threadIdx.x & 31;
    int b = blockIdx.x * 8 + warp;
    __shared__ float s_row[8];
    int t = d_TT[b];
    int tm1 = (t > 0) ? t - 1 : 0;
    const float* outp = d_OUT + (size_t)b * NPAD2;

    float g = 0.f;
    if (lane < NNUM) { float d = noise[b * NNUM + lane] - outp[lane]; g = d * d; }

    float kl = 0.f, dec = 0.f;
    if (lane < NCAT) {
        int hot = d_CAT[b * NCAT + lane];
        int sm  = d_SAMP[b * NCAT + lane];
        const float* oc = outp + NNUM + lane * KCLS;
        float v[KCLS];
        float mx = -1e30f;
        #pragma unroll
        for (int k = 0; k < KCLS; k++) { v[k] = oc[k]; mx = fmaxf(mx, v[k]); }
        float se = 0.f;
        #pragma unroll
        for (int k = 0; k < KCLS; k++) se += expf(v[k] - mx);
        float lse = mx + logf(se);

        float PH = laddexp(d_LOG_A[t], d_LOG_1M_A[t] - LOGK_F);
        float PO = laddexp(CL_F + d_LOG_A[t], d_LOG_1M_A[t] - LOGK_F);
        float H1, O1;
        if (t == 0) { H1 = 0.f; O1 = CL_F; }
        else {
            H1 = laddexp(d_LOG_CA[tm1], d_LOG_1M_CA[tm1] - LOGK_F);
            O1 = laddexp(CL_F + d_LOG_CA[tm1], d_LOG_1M_CA[tm1] - LOGK_F);
        }

        float unm[KCLS], unt[KCLS];
        float mmax = -1e30f, tmax = -1e30f;
        #pragma unroll
        for (int k = 0; k < KCLS; k++) {
            float lx0 = v[k] - lse;
            float ev  = (t == 0) ? lx0
                                 : laddexp(lx0 + d_LOG_CA[tm1], d_LOG_1M_CA[tm1] - LOGK_F);
            float pk  = (k == sm) ? PH : PO;
            float um = ev + pk;            unm[k] = um; mmax = fmaxf(mmax, um);
            float ut = ((k == hot) ? H1 : O1) + pk; unt[k] = ut; tmax = fmaxf(tmax, ut);
        }
        float ms = 0.f, ts = 0.f;
        #pragma unroll
        for (int k = 0; k < KCLS; k++) { ms += expf(unm[k] - mmax); ts += expf(unt[k] - tmax); }
        float mlse = mmax + logf(ms), tlse = tmax + logf(ts);
        float EXPL = expf(CL_F);
        #pragma unroll
        for (int k = 0; k < KCLS; k++) {
            float lt = unt[k] - tlse, lm = unm[k] - mlse;
            kl  += expf(lt) * (lt - lm);
            dec -= ((k == hot) ? 1.0f : EXPL) * lm;
        }
    }

    #pragma unroll
    for (int o = 16; o; o >>= 1) {
        g   += __shfl_xor_sync(0xffffffffu, g, o);
        kl  += __shfl_xor_sync(0xffffffffu, kl, o);
        dec += __shfl_xor_sync(0xffffffffu, dec, o);
    }
    if (lane == 0) {
        float Lt = (t == 0) ? dec : kl;
        s_row[warp] = (Lt + d_KLP) * (1.0f / ((float)NCAT * (float)BATCH))
                    + g * (1.0f / ((float)NNUM * (float)BATCH));
    }
    __syncthreads();
    if (threadIdx.x == 0) {
        float s = 0.f;
        #pragma unroll
        for (int i = 0; i < 8; i++) s += s_row[i];
        d_PART[blockIdx.x] = s;
    }
}

__global__ void final_kernel(float* __restrict__ out) {
    __shared__ float s[256];
    float a = 0.f;
    for (int i = threadIdx.x; i < BATCH / 8; i += 256) a += d_PART[i];
    s[threadIdx.x] = a;
    __syncthreads();
    for (int st = 128; st; st >>= 1) {
        if (threadIdx.x < st) s[threadIdx.x] += s[threadIdx.x + st];
        __syncthreads();
    }
    if (threadIdx.x == 0) out[0] = s[0];
}

// ---------------- launch ----------------
extern "C" void kernel_launch(void* const* d_in, const int* in_sizes, int n_in,
                              void* d_out, int out_size) {
    const float* x_num   = (const float*)d_in[0];
    const int*   x_cat_r = (const int*)  d_in[1];
    const int*   t_r     = (const int*)  d_in[2];
    const float* noise   = (const float*)d_in[3];
    const float* gumbel  = (const float*)d_in[4];
    const float* te_w1   = (const float*)d_in[5];
    const float* te_b1   = (const float*)d_in[6];
    const float* te_w2   = (const float*)d_in[7];
    const float* te_b2   = (const float*)d_in[8];
    const float* proj_w  = (const float*)d_in[9];
    const float* proj_b  = (const float*)d_in[10];
    const float* mlp_w1  = (const float*)d_in[11];
    const float* mlp_b1  = (const float*)d_in[12];
    const float* mlp_w2  = (const float*)d_in[13];
    const float* mlp_b2  = (const float*)d_in[14];
    float* out = (float*)d_out;

    cudaFuncSetAttribute(mma_gemm, cudaFuncAttributeMaxDynamicSharedMemorySize, GSMEM_BYTES);
    cudaFuncSetAttribute(mma_gemm64, cudaFuncAttributeMaxDynamicSharedMemorySize, GSMEM64);

    __nv_bfloat16 *pE0H, *pE0L, *pE1H, *pE1L;
    __nv_bfloat16 *pW1H, *pW1L, *pW2H, *pW2L, *pM1H, *pM1L, *pM2H, *pM2L, *pPJH, *pPJL;
    __nv_bfloat16 *pXIH, *pXIL, *pHH, *pHL, *pUH, *pUL;
    float *pEMB, *pOUT, *pB2;
    cudaGetSymbolAddress((void**)&pE0H, d_E0H); cudaGetSymbolAddress((void**)&pE0L, d_E0L);
    cudaGetSymbolAddress((void**)&pE1H, d_E1H); cudaGetSymbolAddress((void**)&pE1L, d_E1L);
    cudaGetSymbolAddress((void**)&pW1H, d_W1TH); cudaGetSymbolAddress((void**)&pW1L, d_W1TL);
    cudaGetSymbolAddress((void**)&pW2H, d_W2TH); cudaGetSymbolAddress((void**)&pW2L, d_W2TL);
    cudaGetSymbolAddress((void**)&pM1H, d_M1TH); cudaGetSymbolAddress((void**)&pM1L, d_M1TL);
    cudaGetSymbolAddress((void**)&pM2H, d_M2TH); cudaGetSymbolAddress((void**)&pM2L, d_M2TL);
    cudaGetSymbolAddress((void**)&pPJH, d_PJTH); cudaGetSymbolAddress((void**)&pPJL, d_PJTL);
    cudaGetSymbolAddress((void**)&pXIH, d_XINH); cudaGetSymbolAddress((void**)&pXIL, d_XINL);
    cudaGetSymbolAddress((void**)&pHH, d_HH); cudaGetSymbolAddress((void**)&pHL, d_HL);
    cudaGetSymbolAddress((void**)&pUH, d_UH); cudaGetSymbolAddress((void**)&pUL, d_UL);
    cudaGetSymbolAddress((void**)&pEMB, d_EMB); cudaGetSymbolAddress((void**)&pOUT, d_OUT);
    cudaGetSymbolAddress((void**)&pB2, d_B2P);

    sched_kernel<<<1, 1024>>>();                                      // our 1
    detect_kernel<<<1, 32>>>(t_r, x_cat_r);                           // our 2
    prep_kernel<<<9632, dim3(32, 8)>>>(t_r, x_cat_r, mlp_b2,
                                       te_w1, te_w2, mlp_w1, mlp_w2, proj_w); // our 3

    // te MLP over 1024 (padded) unique timesteps — M64 tiles (grid 128)
    mma_gemm64<<<dim3(DIMT / 128, TPAD / 64), 256, GSMEM64>>>(
        pE0H, pE0L, pW1H, pW1L, te_b1, nullptr, pE1H, pE1L, DIMT, DIMT, /*silu*/2);
    mma_gemm64<<<dim3(DIMT / 128, TPAD / 64), 256, GSMEM64>>>(
        pE1H, pE1L, pW2H, pW2L, te_b2, pEMB, nullptr, nullptr, DIMT, DIMT, /*fp32*/0);

    build_xin_kernel<<<BATCH, 128>>>(x_num, noise, gumbel);

    // proj: h = x_in@proj_w + proj_b + emb[t]   -> hi/lo  (K = 416)
    mma_gemm<<<dim3(DIMT / 128, BATCH / 128), 256, GSMEM_BYTES>>>(
        pXIH, pXIL, pPJH, pPJL, proj_b, nullptr, pHH, pHL, pEMB, KPAD, DIMT, /*emb*/3);
    // mlp1: relu -> hi/lo
    mma_gemm<<<dim3(HIDN / 128, BATCH / 128), 256, GSMEM_BYTES>>>(
        pHH, pHL, pM1H, pM1L, mlp_b1, nullptr, pUH, pUL, nullptr, DIMT, HIDN, /*relu*/1);
    // mlp2: fp32 out (padded to 512)
    mma_gemm<<<dim3(NPAD2 / 128, BATCH / 128), 256, GSMEM_BYTES>>>(
        pUH, pUL, pM2H, pM2L, pB2, pOUT, nullptr, nullptr, nullptr, HIDN, NPAD2, /*fp32*/0);

    loss_kernel<<<BATCH / 8, 256>>>(noise);
    final_kernel<<<1, 256>>>(out);
}